// round 1
// baseline (speedup 1.0000x reference)
#include <cuda_runtime.h>
#include <math.h>

#define NN 10000
#define EE 160000
#define ET (EE + NN)   // 170000 edges incl. self loops

// ---------------- scratch (device globals; no runtime allocation) ----------
__device__ float g_xl[(size_t)NN * 1024];
__device__ float g_xr[(size_t)NN * 1024];
__device__ float g_res[(size_t)NN * 1024];
__device__ float g_h1[(size_t)NN * 1024];
__device__ float g_h2[(size_t)NN * 128];
__device__ float g_h3[(size_t)NN * 128];
__device__ float g_t1[(size_t)NN * 64];
__device__ float g_e[(size_t)EE * 1024];     // per-edge transform (real edges)
__device__ float g_eself[1024];              // shared self-loop edge transform
__device__ float g_logit[(size_t)ET * 8];
__device__ float g_easum[32];
__device__ float g_meanea[32];
__device__ int   g_deg[NN];
__device__ int   g_off[NN + 1];
__device__ int   g_fill[NN];
__device__ int   g_csr[ET];

// ---------------- small setup kernels --------------------------------------
__global__ void zero_kernel() {
    int i = blockIdx.x * blockDim.x + threadIdx.x;
    if (i < NN) { g_deg[i] = 0; g_fill[i] = 0; }
    if (i < 32) g_easum[i] = 0.f;
}

__global__ void colsum_kernel(const float* __restrict__ ea) {
    int lane = threadIdx.x & 31;
    int warp = (blockIdx.x * blockDim.x + threadIdx.x) >> 5;
    int nwarp = (gridDim.x * blockDim.x) >> 5;
    float s = 0.f;
    for (int r = warp; r < EE; r += nwarp) s += ea[(size_t)r * 32 + lane];
    atomicAdd(&g_easum[lane], s);
}

__global__ void meanfin_kernel() {
    int c = threadIdx.x;
    if (c < 32) g_meanea[c] = g_easum[c] / (float)EE;
}

__global__ void hist_kernel(const int* __restrict__ ei) {
    int e = blockIdx.x * blockDim.x + threadIdx.x;
    if (e >= ET) return;
    int dst = (e < EE) ? ei[EE + e] : (e - EE);
    atomicAdd(&g_deg[dst], 1);
}

__global__ void scan_kernel() {
    __shared__ int s[1024];
    int t = threadIdx.x;
    const int CH = 10;  // 1024*10 >= NN
    int base = t * CH;
    int v[CH];
    int loc = 0;
#pragma unroll
    for (int i = 0; i < CH; i++) {
        int idx = base + i;
        v[i] = (idx < NN) ? g_deg[idx] : 0;
        loc += v[i];
    }
    s[t] = loc;
    __syncthreads();
    for (int o = 1; o < 1024; o <<= 1) {
        int x = (t >= o) ? s[t - o] : 0;
        __syncthreads();
        s[t] += x;
        __syncthreads();
    }
    int run = s[t] - loc;  // exclusive prefix for this chunk
#pragma unroll
    for (int i = 0; i < CH; i++) {
        int idx = base + i;
        if (idx < NN) g_off[idx] = run;
        run += v[i];
    }
    if (t == 1023) g_off[NN] = s[1023];
}

__global__ void scatter_kernel(const int* __restrict__ ei) {
    int e = blockIdx.x * blockDim.x + threadIdx.x;
    if (e >= ET) return;
    int dst = (e < EE) ? ei[EE + e] : (e - EE);
    int p = atomicAdd(&g_fill[dst], 1);
    g_csr[g_off[dst] + p] = e;
}

__global__ void eself_kernel(const float* __restrict__ We, int HC) {
    int c = blockIdx.x * blockDim.x + threadIdx.x;
    if (c >= HC) return;
    float s = 0.f;
#pragma unroll
    for (int k = 0; k < 32; k++) s += g_meanea[k] * We[(size_t)k * HC + c];
    g_eself[c] = s;
}

// ---------------- generic SGEMM: C = A[MxK] @ B[KxN] (+bias)(+elu) ---------
// K must be a multiple of 8 (true for all calls: 32/64/128/1024).
#define TM 128
#define TN 128
#define TKK 8
__global__ void gemm_kernel(const float* __restrict__ A, const float* __restrict__ B,
                            const float* __restrict__ bias, float* __restrict__ C,
                            int M, int N, int K, int act) {
    __shared__ __align__(16) float As[TKK][TM];
    __shared__ __align__(16) float Bs[TKK][TN];
    int tid = threadIdx.x;
    int tx = tid & 15, ty = tid >> 4;
    int row0 = blockIdx.y * TM + ty * 8;
    int col0 = blockIdx.x * TN + tx * 8;

    int arow = tid >> 1;
    int acol = (tid & 1) * 4;
    int gArow = blockIdx.y * TM + arow;
    int brow = tid >> 5;
    int bcol = (tid & 31) * 4;
    int gBcol = blockIdx.x * TN + bcol;

    float acc[8][8];
#pragma unroll
    for (int i = 0; i < 8; i++)
#pragma unroll
        for (int j = 0; j < 8; j++) acc[i][j] = 0.f;

    for (int kt = 0; kt < K; kt += TKK) {
        float4 av = make_float4(0.f, 0.f, 0.f, 0.f);
        if (gArow < M) av = *(const float4*)(A + (size_t)gArow * K + kt + acol);
        As[acol + 0][arow] = av.x;
        As[acol + 1][arow] = av.y;
        As[acol + 2][arow] = av.z;
        As[acol + 3][arow] = av.w;

        float4 bv;
        if (gBcol + 3 < N) {
            bv = *(const float4*)(B + (size_t)(kt + brow) * N + gBcol);
        } else {
            float tv[4] = {0.f, 0.f, 0.f, 0.f};
            for (int j = 0; j < 4; j++)
                if (gBcol + j < N) tv[j] = B[(size_t)(kt + brow) * N + gBcol + j];
            bv = make_float4(tv[0], tv[1], tv[2], tv[3]);
        }
        *(float4*)&Bs[brow][bcol] = bv;
        __syncthreads();

#pragma unroll
        for (int k = 0; k < TKK; k++) {
            float a[8], b[8];
            *(float4*)(a)     = *(const float4*)&As[k][ty * 8];
            *(float4*)(a + 4) = *(const float4*)&As[k][ty * 8 + 4];
            *(float4*)(b)     = *(const float4*)&Bs[k][tx * 8];
            *(float4*)(b + 4) = *(const float4*)&Bs[k][tx * 8 + 4];
#pragma unroll
            for (int i = 0; i < 8; i++)
#pragma unroll
                for (int j = 0; j < 8; j++) acc[i][j] += a[i] * b[j];
        }
        __syncthreads();
    }

#pragma unroll
    for (int i = 0; i < 8; i++) {
        int r = row0 + i;
        if (r >= M) continue;
#pragma unroll
        for (int j = 0; j < 8; j++) {
            int c = col0 + j;
            if (c >= N) continue;
            float v = acc[i][j];
            if (bias) v += bias[c];
            if (act == 1) v = v > 0.f ? v : expm1f(v);  // ELU
            C[(size_t)r * N + c] = v;
        }
    }
}

// ---------------- per-edge logits: one warp per edge -----------------------
template <int H>
__global__ void logits_kernel(const float* __restrict__ xl, const float* __restrict__ xr,
                              const float* __restrict__ eedge, const float* __restrict__ eself,
                              const float* __restrict__ att, const int* __restrict__ ei,
                              float* __restrict__ logit) {
    const int HC = H * 128;
    __shared__ float s_att[H * 128];
    for (int i = threadIdx.x; i < HC; i += blockDim.x) s_att[i] = att[i];
    __syncthreads();

    int gw = (blockIdx.x * blockDim.x + threadIdx.x) >> 5;
    int lane = threadIdx.x & 31;
    if (gw >= ET) return;
    int e = gw;
    int src = (e < EE) ? ei[e] : (e - EE);
    int dst = (e < EE) ? ei[EE + e] : (e - EE);
    const float4* pl = (const float4*)(xl + (size_t)src * HC);
    const float4* pr = (const float4*)(xr + (size_t)dst * HC);
    const float4* pe = (const float4*)((e < EE) ? (eedge + (size_t)e * HC) : eself);
    const float4* pa = (const float4*)s_att;

#pragma unroll
    for (int h = 0; h < H; h++) {
        int j = h * 32 + lane;
        float4 a = pl[j], b = pr[j], c = pe[j], w = pa[j];
        float u, p = 0.f;
        u = a.x + b.x + c.x; u = u > 0.f ? u : 0.2f * u; p += u * w.x;
        u = a.y + b.y + c.y; u = u > 0.f ? u : 0.2f * u; p += u * w.y;
        u = a.z + b.z + c.z; u = u > 0.f ? u : 0.2f * u; p += u * w.z;
        u = a.w + b.w + c.w; u = u > 0.f ? u : 0.2f * u; p += u * w.w;
#pragma unroll
        for (int o = 16; o; o >>= 1) p += __shfl_xor_sync(0xffffffffu, p, o);
        if (lane == 0) logit[(size_t)e * H + h] = p;
    }
}

// ---------------- node-parallel segment softmax + aggregation --------------
// ACT: 0 none, 1 leaky_relu(0.2), 2 elu
template <int H, int CONCAT, int ACT>
__global__ void agg_kernel(const float* __restrict__ xl, const float* __restrict__ logit,
                           const int* __restrict__ ei, const float* __restrict__ bias,
                           const float* __restrict__ res, float* __restrict__ out) {
    const int HC = H * 128;
    int n = blockIdx.x, t = threadIdx.x;  // 128 threads: t = channel-within-head
    int beg = g_off[n];
    int deg = g_off[n + 1] - beg;
    __shared__ float red[128];
    __shared__ float s_m[H], s_z[H];

    // phase 1: per-head max
    float lm[H];
#pragma unroll
    for (int h = 0; h < H; h++) lm[h] = -1e30f;
    for (int i = t; i < deg; i += 128) {
        int e = g_csr[beg + i];
#pragma unroll
        for (int h = 0; h < H; h++) lm[h] = fmaxf(lm[h], logit[(size_t)e * H + h]);
    }
#pragma unroll
    for (int h = 0; h < H; h++) {
        red[t] = lm[h];
        __syncthreads();
        for (int s = 64; s > 0; s >>= 1) {
            if (t < s) red[t] = fmaxf(red[t], red[t + s]);
            __syncthreads();
        }
        if (t == 0) s_m[h] = red[0];
        __syncthreads();
    }

    // phase 2: per-head denom
    float lz[H];
#pragma unroll
    for (int h = 0; h < H; h++) lz[h] = 0.f;
    for (int i = t; i < deg; i += 128) {
        int e = g_csr[beg + i];
#pragma unroll
        for (int h = 0; h < H; h++) lz[h] += __expf(logit[(size_t)e * H + h] - s_m[h]);
    }
#pragma unroll
    for (int h = 0; h < H; h++) {
        red[t] = lz[h];
        __syncthreads();
        for (int s = 64; s > 0; s >>= 1) {
            if (t < s) red[t] += red[t + s];
            __syncthreads();
        }
        if (t == 0) s_z[h] = red[0];
        __syncthreads();
    }

    // phase 3: weighted aggregation (all threads walk the edge list together)
    float acc[H];
#pragma unroll
    for (int h = 0; h < H; h++) acc[h] = 0.f;
    for (int i = 0; i < deg; i++) {
        int e = g_csr[beg + i];
        int src = (e < EE) ? ei[e] : (e - EE);
        const float* xp = xl + (size_t)src * HC;
#pragma unroll
        for (int h = 0; h < H; h++) {
            float w = __expf(logit[(size_t)e * H + h] - s_m[h]);
            acc[h] += w * xp[h * 128 + t];
        }
    }

    if (CONCAT) {
#pragma unroll
        for (int h = 0; h < H; h++) {
            float v = acc[h] / (s_z[h] + 1e-16f) + bias[h * 128 + t];
            if (res) v += res[(size_t)n * HC + h * 128 + t];
            if (ACT == 1) v = v > 0.f ? v : 0.2f * v;
            else if (ACT == 2) v = v > 0.f ? v : expm1f(v);
            out[(size_t)n * HC + h * 128 + t] = v;
        }
    } else {
        float v = 0.f;
#pragma unroll
        for (int h = 0; h < H; h++) v += acc[h] / (s_z[h] + 1e-16f);
        v = v * (1.f / H) + bias[t];
        if (ACT == 1) v = v > 0.f ? v : 0.2f * v;
        else if (ACT == 2) v = v > 0.f ? v : expm1f(v);
        out[(size_t)n * 128 + t] = v;
    }
}

// ---------------- final tiny GEMM [NN,64]x[64,3] ----------------------------
__global__ void head2_kernel(const float* __restrict__ t1, const float* __restrict__ W,
                             const float* __restrict__ b, float* __restrict__ out) {
    int gw = (blockIdx.x * blockDim.x + threadIdx.x) >> 5;
    int lane = threadIdx.x & 31;
    if (gw >= NN) return;
    float a0 = t1[(size_t)gw * 64 + lane];
    float a1 = t1[(size_t)gw * 64 + 32 + lane];
#pragma unroll
    for (int j = 0; j < 3; j++) {
        float p = a0 * W[lane * 3 + j] + a1 * W[(lane + 32) * 3 + j];
#pragma unroll
        for (int o = 16; o; o >>= 1) p += __shfl_xor_sync(0xffffffffu, p, o);
        if (lane == 0) out[(size_t)gw * 3 + j] = p + b[j];
    }
}

// ---------------- host orchestration ---------------------------------------
static inline void gemm(const float* A, const float* B, const float* bias, float* C,
                        int M, int N, int K, int act) {
    dim3 g((N + TN - 1) / TN, (M + TM - 1) / TM);
    gemm_kernel<<<g, 256>>>(A, B, bias, C, M, N, K, act);
}

extern "C" void kernel_launch(void* const* d_in, const int* in_sizes, int n_in,
                              void* d_out, int out_size) {
    const float* x    = (const float*)d_in[0];
    const int*   ei   = (const int*)d_in[1];
    const float* ea   = (const float*)d_in[2];
    const float* Wl1  = (const float*)d_in[3];
    const float* bl1  = (const float*)d_in[4];
    const float* Wr1  = (const float*)d_in[5];
    const float* br1  = (const float*)d_in[6];
    const float* We1  = (const float*)d_in[7];
    const float* att1 = (const float*)d_in[8];
    const float* bo1  = (const float*)d_in[9];
    const float* Wl2  = (const float*)d_in[10];
    const float* bl2  = (const float*)d_in[11];
    const float* Wr2  = (const float*)d_in[12];
    const float* br2  = (const float*)d_in[13];
    const float* We2  = (const float*)d_in[14];
    const float* att2 = (const float*)d_in[15];
    const float* bo2  = (const float*)d_in[16];
    const float* Wl3  = (const float*)d_in[17];
    const float* bl3  = (const float*)d_in[18];
    const float* Wr3  = (const float*)d_in[19];
    const float* br3  = (const float*)d_in[20];
    const float* We3  = (const float*)d_in[21];
    const float* att3 = (const float*)d_in[22];
    const float* bo3  = (const float*)d_in[23];
    const float* Wres = (const float*)d_in[24];
    const float* bres = (const float*)d_in[25];
    const float* Wc1  = (const float*)d_in[26];
    const float* bc1  = (const float*)d_in[27];
    const float* Wc2  = (const float*)d_in[28];
    const float* bc2  = (const float*)d_in[29];
    float* out = (float*)d_out;

    float *p_xl, *p_xr, *p_res, *p_h1, *p_h2, *p_h3, *p_t1, *p_e, *p_eself, *p_lg;
    cudaGetSymbolAddress((void**)&p_xl, g_xl);
    cudaGetSymbolAddress((void**)&p_xr, g_xr);
    cudaGetSymbolAddress((void**)&p_res, g_res);
    cudaGetSymbolAddress((void**)&p_h1, g_h1);
    cudaGetSymbolAddress((void**)&p_h2, g_h2);
    cudaGetSymbolAddress((void**)&p_h3, g_h3);
    cudaGetSymbolAddress((void**)&p_t1, g_t1);
    cudaGetSymbolAddress((void**)&p_e, g_e);
    cudaGetSymbolAddress((void**)&p_eself, g_eself);
    cudaGetSymbolAddress((void**)&p_lg, g_logit);

    // graph setup: mean edge attr + CSR by dst
    zero_kernel<<<(NN + 255) / 256, 256>>>();
    colsum_kernel<<<256, 256>>>(ea);
    hist_kernel<<<(ET + 255) / 256, 256>>>(ei);
    meanfin_kernel<<<1, 32>>>();
    scan_kernel<<<1, 1024>>>();
    scatter_kernel<<<(ET + 255) / 256, 256>>>(ei);

    const int LOG_GRID = (ET * 32 + 255) / 256;

    // ---- layer 1: H=8, C=128, concat; then +res, leaky_relu ----
    gemm(x, Wl1, bl1, p_xl, NN, 1024, 128, 0);
    gemm(x, Wr1, br1, p_xr, NN, 1024, 128, 0);
    gemm(x, Wres, bres, p_res, NN, 1024, 128, 0);
    gemm(ea, We1, nullptr, p_e, EE, 1024, 32, 0);
    eself_kernel<<<(1024 + 255) / 256, 256>>>(We1, 1024);
    logits_kernel<8><<<LOG_GRID, 256>>>(p_xl, p_xr, p_e, p_eself, att1, ei, p_lg);
    agg_kernel<8, 1, 1><<<NN, 128>>>(p_xl, p_lg, ei, bo1, p_res, p_h1);

    // ---- layer 2: H=4, C=128, mean; elu ----
    gemm(p_h1, Wl2, bl2, p_xl, NN, 512, 1024, 0);
    gemm(p_h1, Wr2, br2, p_xr, NN, 512, 1024, 0);
    gemm(ea, We2, nullptr, p_e, EE, 512, 32, 0);
    eself_kernel<<<(512 + 255) / 256, 256>>>(We2, 512);
    logits_kernel<4><<<LOG_GRID, 256>>>(p_xl, p_xr, p_e, p_eself, att2, ei, p_lg);
    agg_kernel<4, 0, 2><<<NN, 128>>>(p_xl, p_lg, ei, bo2, nullptr, p_h2);

    // ---- layer 3: H=1, C=128, concat; elu ----
    gemm(p_h2, Wl3, bl3, p_xl, NN, 128, 128, 0);
    gemm(p_h2, Wr3, br3, p_xr, NN, 128, 128, 0);
    gemm(ea, We3, nullptr, p_e, EE, 128, 32, 0);
    eself_kernel<<<1, 128>>>(We3, 128);
    logits_kernel<1><<<LOG_GRID, 256>>>(p_xl, p_xr, p_e, p_eself, att3, ei, p_lg);
    agg_kernel<1, 1, 2><<<NN, 128>>>(p_xl, p_lg, ei, bo3, nullptr, p_h3);

    // ---- head MLP ----
    gemm(p_h3, Wc1, bc1, p_t1, NN, 64, 128, 1);  // + elu
    head2_kernel<<<(NN * 32 + 255) / 256, 256>>>(p_t1, Wc2, bc2, out);
}

// round 3
// speedup vs baseline: 1.8749x; 1.8749x over previous
#include <cuda_runtime.h>
#include <math.h>

#define NN 10000
#define EE 160000
#define ET (EE + NN)   // 170000 edges incl. self loops

// ---------------- scratch (device globals; no runtime allocation) ----------
__device__ float g_xl[(size_t)NN * 1024];
__device__ float g_xr[(size_t)NN * 1024];
__device__ float g_res[(size_t)NN * 1024];
__device__ float g_h1[(size_t)NN * 1024];
__device__ float g_h2[(size_t)NN * 128];
__device__ float g_h3[(size_t)NN * 128];
__device__ float g_t1[(size_t)NN * 64];
__device__ float g_e[(size_t)EE * 1024];     // per-edge transform (real edges)
__device__ float g_eself[1024];              // shared self-loop edge transform
__device__ float g_logit[(size_t)ET * 8];
__device__ float g_easum[32];
__device__ float g_meanea[32];
__device__ int   g_deg[NN];
__device__ int   g_off[NN + 1];
__device__ int   g_fill[NN];
__device__ int   g_csr[ET];

// ---------------- small setup kernels --------------------------------------
__global__ void zero_kernel() {
    int i = blockIdx.x * blockDim.x + threadIdx.x;
    if (i < NN) { g_deg[i] = 0; g_fill[i] = 0; }
    if (i < 32) g_easum[i] = 0.f;
}

__global__ void colsum_kernel(const float* __restrict__ ea) {
    int lane = threadIdx.x & 31;
    int warp = (blockIdx.x * blockDim.x + threadIdx.x) >> 5;
    int nwarp = (gridDim.x * blockDim.x) >> 5;
    float s = 0.f;
    for (int r = warp; r < EE; r += nwarp) s += ea[(size_t)r * 32 + lane];
    atomicAdd(&g_easum[lane], s);
}

__global__ void meanfin_kernel() {
    int c = threadIdx.x;
    if (c < 32) g_meanea[c] = g_easum[c] / (float)EE;
}

__global__ void hist_kernel(const int* __restrict__ ei) {
    int e = blockIdx.x * blockDim.x + threadIdx.x;
    if (e >= ET) return;
    int dst = (e < EE) ? ei[EE + e] : (e - EE);
    atomicAdd(&g_deg[dst], 1);
}

__global__ void scan_kernel() {
    __shared__ int s[1024];
    int t = threadIdx.x;
    const int CH = 10;  // 1024*10 >= NN
    int base = t * CH;
    int v[CH];
    int loc = 0;
#pragma unroll
    for (int i = 0; i < CH; i++) {
        int idx = base + i;
        v[i] = (idx < NN) ? g_deg[idx] : 0;
        loc += v[i];
    }
    s[t] = loc;
    __syncthreads();
    for (int o = 1; o < 1024; o <<= 1) {
        int x = (t >= o) ? s[t - o] : 0;
        __syncthreads();
        s[t] += x;
        __syncthreads();
    }
    int run = s[t] - loc;  // exclusive prefix for this chunk
#pragma unroll
    for (int i = 0; i < CH; i++) {
        int idx = base + i;
        if (idx < NN) g_off[idx] = run;
        run += v[i];
    }
    if (t == 1023) g_off[NN] = s[1023];
}

__global__ void scatter_kernel(const int* __restrict__ ei) {
    int e = blockIdx.x * blockDim.x + threadIdx.x;
    if (e >= ET) return;
    int dst = (e < EE) ? ei[EE + e] : (e - EE);
    int p = atomicAdd(&g_fill[dst], 1);
    g_csr[g_off[dst] + p] = e;
}

__global__ void eself_kernel(const float* __restrict__ We, int HC) {
    int c = blockIdx.x * blockDim.x + threadIdx.x;
    if (c >= HC) return;
    float s = 0.f;
#pragma unroll
    for (int k = 0; k < 32; k++) s += g_meanea[k] * We[(size_t)k * HC + c];
    g_eself[c] = s;
}

// ---------------- TF32 tensor-core GEMM ------------------------------------
// C = A[MxK] @ B[KxN] (+bias)(+elu). K must be a multiple of 16.
#define BM 128
#define BN 128
#define BK 16

__device__ __forceinline__ unsigned f2tf(float x) {
    unsigned r;
    asm("cvt.rna.tf32.f32 %0, %1;" : "=r"(r) : "f"(x));
    return r;
}

// swizzled A-smem accessor: As[k][m] with row index xor'd so both the
// transposed stores and the fragment loads are bank-conflict-free.
#define AS(k, m) As[k][(m) ^ ((((k) >> 2) & 3) << 3)]

__global__ __launch_bounds__(256, 2)
void gemm_tf32_kernel(const float* __restrict__ A, const float* __restrict__ B,
                      const float* __restrict__ bias, float* __restrict__ C,
                      int M, int N, int K, int act) {
    __shared__ unsigned As[BK][BM + 8];   // pitch 136: k*136 % 32 == (k&3)*8
    __shared__ unsigned Bs[BK][BN + 8];

    int tid = threadIdx.x;
    int warp = tid >> 5, lane = tid & 31;
    int wm = warp >> 2, wn = warp & 3;     // 2 x 4 warp grid; warp tile 64x32
    int gid = lane >> 2, tig = lane & 3;   // mma group id / thread-in-group
    int m0 = blockIdx.y * BM, n0 = blockIdx.x * BN;

    float acc[4][4][4];
#pragma unroll
    for (int mt = 0; mt < 4; mt++)
#pragma unroll
        for (int nt = 0; nt < 4; nt++)
#pragma unroll
            for (int i = 0; i < 4; i++) acc[mt][nt][i] = 0.f;

    for (int kt = 0; kt < K; kt += BK) {
        // --- load A tile 128x16 (transpose into As[k][m], tf32-converted) ---
#pragma unroll
        for (int p = 0; p < 2; p++) {
            int linear = p * 1024 + tid * 4;
            int row = linear >> 4, col = linear & 15;
            float4 v = make_float4(0.f, 0.f, 0.f, 0.f);
            if (m0 + row < M)
                v = *(const float4*)(A + (size_t)(m0 + row) * K + kt + col);
            AS(col + 0, row) = f2tf(v.x);
            AS(col + 1, row) = f2tf(v.y);
            AS(col + 2, row) = f2tf(v.z);
            AS(col + 3, row) = f2tf(v.w);
        }
        // --- load B tile 16x128 ---
#pragma unroll
        for (int p = 0; p < 2; p++) {
            int linear = p * 1024 + tid * 4;
            int row = linear >> 7, col = linear & 127;
            float4 v;
            if (n0 + col + 3 < N) {
                v = *(const float4*)(B + (size_t)(kt + row) * N + n0 + col);
            } else {
                float t[4] = {0.f, 0.f, 0.f, 0.f};
                for (int j = 0; j < 4; j++)
                    if (n0 + col + j < N) t[j] = B[(size_t)(kt + row) * N + n0 + col + j];
                v = make_float4(t[0], t[1], t[2], t[3]);
            }
            Bs[row][col + 0] = f2tf(v.x);
            Bs[row][col + 1] = f2tf(v.y);
            Bs[row][col + 2] = f2tf(v.z);
            Bs[row][col + 3] = f2tf(v.w);
        }
        __syncthreads();

#pragma unroll
        for (int ks = 0; ks < 2; ks++) {
            int k0 = ks * 8;
            unsigned af[4][4], bf[4][2];
#pragma unroll
            for (int mt = 0; mt < 4; mt++) {
                int m = wm * 64 + mt * 16;
                af[mt][0] = AS(k0 + tig,     m + gid);
                af[mt][1] = AS(k0 + tig,     m + gid + 8);
                af[mt][2] = AS(k0 + tig + 4, m + gid);
                af[mt][3] = AS(k0 + tig + 4, m + gid + 8);
            }
#pragma unroll
            for (int nt = 0; nt < 4; nt++) {
                int n = wn * 32 + nt * 8;
                bf[nt][0] = Bs[k0 + tig][n + gid];
                bf[nt][1] = Bs[k0 + tig + 4][n + gid];
            }
#pragma unroll
            for (int mt = 0; mt < 4; mt++)
#pragma unroll
                for (int nt = 0; nt < 4; nt++) {
                    asm volatile(
                        "mma.sync.aligned.m16n8k8.row.col.f32.tf32.tf32.f32 "
                        "{%0,%1,%2,%3}, {%4,%5,%6,%7}, {%8,%9}, {%0,%1,%2,%3};"
                        : "+f"(acc[mt][nt][0]), "+f"(acc[mt][nt][1]),
                          "+f"(acc[mt][nt][2]), "+f"(acc[mt][nt][3])
                        : "r"(af[mt][0]), "r"(af[mt][1]), "r"(af[mt][2]), "r"(af[mt][3]),
                          "r"(bf[nt][0]), "r"(bf[nt][1]));
                }
        }
        __syncthreads();
    }

    // --- epilogue ---
#pragma unroll
    for (int mt = 0; mt < 4; mt++) {
        int rb = m0 + wm * 64 + mt * 16 + gid;
#pragma unroll
        for (int nt = 0; nt < 4; nt++) {
            int cb = n0 + wn * 32 + nt * 8 + tig * 2;
#pragma unroll
            for (int half = 0; half < 2; half++) {
                int r = rb + half * 8;
                if (r >= M) continue;
#pragma unroll
                for (int j = 0; j < 2; j++) {
                    int c = cb + j;
                    if (c >= N) continue;
                    float v = acc[mt][nt][half * 2 + j];
                    if (bias) v += bias[c];
                    if (act == 1) v = v > 0.f ? v : expm1f(v);  // ELU
                    C[(size_t)r * N + c] = v;
                }
            }
        }
    }
}

// ---------------- per-edge logits: one warp per edge -----------------------
template <int H>
__global__ void logits_kernel(const float* __restrict__ xl, const float* __restrict__ xr,
                              const float* __restrict__ eedge, const float* __restrict__ eself,
                              const float* __restrict__ att, const int* __restrict__ ei,
                              float* __restrict__ logit) {
    const int HC = H * 128;
    __shared__ float s_att[H * 128];
    for (int i = threadIdx.x; i < HC; i += blockDim.x) s_att[i] = att[i];
    __syncthreads();

    int gw = (blockIdx.x * blockDim.x + threadIdx.x) >> 5;
    int lane = threadIdx.x & 31;
    if (gw >= ET) return;
    int e = gw;
    int src = (e < EE) ? ei[e] : (e - EE);
    int dst = (e < EE) ? ei[EE + e] : (e - EE);
    const float4* pl = (const float4*)(xl + (size_t)src * HC);
    const float4* pr = (const float4*)(xr + (size_t)dst * HC);
    const float4* pe = (const float4*)((e < EE) ? (eedge + (size_t)e * HC) : eself);
    const float4* pa = (const float4*)s_att;

#pragma unroll
    for (int h = 0; h < H; h++) {
        int j = h * 32 + lane;
        float4 a = pl[j], b = pr[j], c = pe[j], w = pa[j];
        float u, p = 0.f;
        u = a.x + b.x + c.x; u = u > 0.f ? u : 0.2f * u; p += u * w.x;
        u = a.y + b.y + c.y; u = u > 0.f ? u : 0.2f * u; p += u * w.y;
        u = a.z + b.z + c.z; u = u > 0.f ? u : 0.2f * u; p += u * w.z;
        u = a.w + b.w + c.w; u = u > 0.f ? u : 0.2f * u; p += u * w.w;
#pragma unroll
        for (int o = 16; o; o >>= 1) p += __shfl_xor_sync(0xffffffffu, p, o);
        if (lane == 0) logit[(size_t)e * H + h] = p;
    }
}

// ---------------- node-parallel segment softmax + aggregation --------------
// ACT: 0 none, 1 leaky_relu(0.2), 2 elu
template <int H, int CONCAT, int ACT>
__global__ void agg_kernel(const float* __restrict__ xl, const float* __restrict__ logit,
                           const int* __restrict__ ei, const float* __restrict__ bias,
                           const float* __restrict__ res, float* __restrict__ out) {
    const int HC = H * 128;
    int n = blockIdx.x, t = threadIdx.x;  // 128 threads: t = channel-within-head
    int beg = g_off[n];
    int deg = g_off[n + 1] - beg;
    __shared__ float red[128];
    __shared__ float s_m[H], s_z[H];

    // phase 1: per-head max
    float lm[H];
#pragma unroll
    for (int h = 0; h < H; h++) lm[h] = -1e30f;
    for (int i = t; i < deg; i += 128) {
        int e = g_csr[beg + i];
#pragma unroll
        for (int h = 0; h < H; h++) lm[h] = fmaxf(lm[h], logit[(size_t)e * H + h]);
    }
#pragma unroll
    for (int h = 0; h < H; h++) {
        red[t] = lm[h];
        __syncthreads();
        for (int s = 64; s > 0; s >>= 1) {
            if (t < s) red[t] = fmaxf(red[t], red[t + s]);
            __syncthreads();
        }
        if (t == 0) s_m[h] = red[0];
        __syncthreads();
    }

    // phase 2: per-head denom
    float lz[H];
#pragma unroll
    for (int h = 0; h < H; h++) lz[h] = 0.f;
    for (int i = t; i < deg; i += 128) {
        int e = g_csr[beg + i];
#pragma unroll
        for (int h = 0; h < H; h++) lz[h] += __expf(logit[(size_t)e * H + h] - s_m[h]);
    }
#pragma unroll
    for (int h = 0; h < H; h++) {
        red[t] = lz[h];
        __syncthreads();
        for (int s = 64; s > 0; s >>= 1) {
            if (t < s) red[t] += red[t + s];
            __syncthreads();
        }
        if (t == 0) s_z[h] = red[0];
        __syncthreads();
    }

    // phase 3: weighted aggregation (all threads walk the edge list together)
    float acc[H];
#pragma unroll
    for (int h = 0; h < H; h++) acc[h] = 0.f;
    for (int i = 0; i < deg; i++) {
        int e = g_csr[beg + i];
        int src = (e < EE) ? ei[e] : (e - EE);
        const float* xp = xl + (size_t)src * HC;
#pragma unroll
        for (int h = 0; h < H; h++) {
            float w = __expf(logit[(size_t)e * H + h] - s_m[h]);
            acc[h] += w * xp[h * 128 + t];
        }
    }

    if (CONCAT) {
#pragma unroll
        for (int h = 0; h < H; h++) {
            float v = acc[h] / (s_z[h] + 1e-16f) + bias[h * 128 + t];
            if (res) v += res[(size_t)n * HC + h * 128 + t];
            if (ACT == 1) v = v > 0.f ? v : 0.2f * v;
            else if (ACT == 2) v = v > 0.f ? v : expm1f(v);
            out[(size_t)n * HC + h * 128 + t] = v;
        }
    } else {
        float v = 0.f;
#pragma unroll
        for (int h = 0; h < H; h++) v += acc[h] / (s_z[h] + 1e-16f);
        v = v * (1.f / H) + bias[t];
        if (ACT == 1) v = v > 0.f ? v : 0.2f * v;
        else if (ACT == 2) v = v > 0.f ? v : expm1f(v);
        out[(size_t)n * 128 + t] = v;
    }
}

// ---------------- final tiny GEMM [NN,64]x[64,3] ----------------------------
__global__ void head2_kernel(const float* __restrict__ t1, const float* __restrict__ W,
                             const float* __restrict__ b, float* __restrict__ out) {
    int gw = (blockIdx.x * blockDim.x + threadIdx.x) >> 5;
    int lane = threadIdx.x & 31;
    if (gw >= NN) return;
    float a0 = t1[(size_t)gw * 64 + lane];
    float a1 = t1[(size_t)gw * 64 + 32 + lane];
#pragma unroll
    for (int j = 0; j < 3; j++) {
        float p = a0 * W[lane * 3 + j] + a1 * W[(lane + 32) * 3 + j];
#pragma unroll
        for (int o = 16; o; o >>= 1) p += __shfl_xor_sync(0xffffffffu, p, o);
        if (lane == 0) out[(size_t)gw * 3 + j] = p + b[j];
    }
}

// ---------------- host orchestration ---------------------------------------
static inline void gemm(const float* A, const float* B, const float* bias, float* C,
                        int M, int N, int K, int act) {
    dim3 g((N + BN - 1) / BN, (M + BM - 1) / BM);
    gemm_tf32_kernel<<<g, 256>>>(A, B, bias, C, M, N, K, act);
}

extern "C" void kernel_launch(void* const* d_in, const int* in_sizes, int n_in,
                              void* d_out, int out_size) {
    const float* x    = (const float*)d_in[0];
    const int*   ei   = (const int*)d_in[1];
    const float* ea   = (const float*)d_in[2];
    const float* Wl1  = (const float*)d_in[3];
    const float* bl1  = (const float*)d_in[4];
    const float* Wr1  = (const float*)d_in[5];
    const float* br1  = (const float*)d_in[6];
    const float* We1  = (const float*)d_in[7];
    const float* att1 = (const float*)d_in[8];
    const float* bo1  = (const float*)d_in[9];
    const float* Wl2  = (const float*)d_in[10];
    const float* bl2  = (const float*)d_in[11];
    const float* Wr2  = (const float*)d_in[12];
    const float* br2  = (const float*)d_in[13];
    const float* We2  = (const float*)d_in[14];
    const float* att2 = (const float*)d_in[15];
    const float* bo2  = (const float*)d_in[16];
    const float* Wl3  = (const float*)d_in[17];
    const float* bl3  = (const float*)d_in[18];
    const float* Wr3  = (const float*)d_in[19];
    const float* br3  = (const float*)d_in[20];
    const float* We3  = (const float*)d_in[21];
    const float* att3 = (const float*)d_in[22];
    const float* bo3  = (const float*)d_in[23];
    const float* Wres = (const float*)d_in[24];
    const float* bres = (const float*)d_in[25];
    const float* Wc1  = (const float*)d_in[26];
    const float* bc1  = (const float*)d_in[27];
    const float* Wc2  = (const float*)d_in[28];
    const float* bc2  = (const float*)d_in[29];
    float* out = (float*)d_out;

    float *p_xl, *p_xr, *p_res, *p_h1, *p_h2, *p_h3, *p_t1, *p_e, *p_eself, *p_lg;
    cudaGetSymbolAddress((void**)&p_xl, g_xl);
    cudaGetSymbolAddress((void**)&p_xr, g_xr);
    cudaGetSymbolAddress((void**)&p_res, g_res);
    cudaGetSymbolAddress((void**)&p_h1, g_h1);
    cudaGetSymbolAddress((void**)&p_h2, g_h2);
    cudaGetSymbolAddress((void**)&p_h3, g_h3);
    cudaGetSymbolAddress((void**)&p_t1, g_t1);
    cudaGetSymbolAddress((void**)&p_e, g_e);
    cudaGetSymbolAddress((void**)&p_eself, g_eself);
    cudaGetSymbolAddress((void**)&p_lg, g_logit);

    // graph setup: mean edge attr + CSR by dst
    zero_kernel<<<(NN + 255) / 256, 256>>>();
    colsum_kernel<<<256, 256>>>(ea);
    hist_kernel<<<(ET + 255) / 256, 256>>>(ei);
    meanfin_kernel<<<1, 32>>>();
    scan_kernel<<<1, 1024>>>();
    scatter_kernel<<<(ET + 255) / 256, 256>>>(ei);

    const int LOG_GRID = (ET * 32 + 255) / 256;

    // ---- layer 1: H=8, C=128, concat; then +res, leaky_relu ----
    gemm(x, Wl1, bl1, p_xl, NN, 1024, 128, 0);
    gemm(x, Wr1, br1, p_xr, NN, 1024, 128, 0);
    gemm(x, Wres, bres, p_res, NN, 1024, 128, 0);
    gemm(ea, We1, nullptr, p_e, EE, 1024, 32, 0);
    eself_kernel<<<(1024 + 255) / 256, 256>>>(We1, 1024);
    logits_kernel<8><<<LOG_GRID, 256>>>(p_xl, p_xr, p_e, p_eself, att1, ei, p_lg);
    agg_kernel<8, 1, 1><<<NN, 128>>>(p_xl, p_lg, ei, bo1, p_res, p_h1);

    // ---- layer 2: H=4, C=128, mean; elu ----
    gemm(p_h1, Wl2, bl2, p_xl, NN, 512, 1024, 0);
    gemm(p_h1, Wr2, br2, p_xr, NN, 512, 1024, 0);
    gemm(ea, We2, nullptr, p_e, EE, 512, 32, 0);
    eself_kernel<<<(512 + 255) / 256, 256>>>(We2, 512);
    logits_kernel<4><<<LOG_GRID, 256>>>(p_xl, p_xr, p_e, p_eself, att2, ei, p_lg);
    agg_kernel<4, 0, 2><<<NN, 128>>>(p_xl, p_lg, ei, bo2, nullptr, p_h2);

    // ---- layer 3: H=1, C=128, concat; elu ----
    gemm(p_h2, Wl3, bl3, p_xl, NN, 128, 128, 0);
    gemm(p_h2, Wr3, br3, p_xr, NN, 128, 128, 0);
    gemm(ea, We3, nullptr, p_e, EE, 128, 32, 0);
    eself_kernel<<<1, 128>>>(We3, 128);
    logits_kernel<1><<<LOG_GRID, 256>>>(p_xl, p_xr, p_e, p_eself, att3, ei, p_lg);
    agg_kernel<1, 1, 2><<<NN, 128>>>(p_xl, p_lg, ei, bo3, nullptr, p_h3);

    // ---- head MLP ----
    gemm(p_h3, Wc1, bc1, p_t1, NN, 64, 128, 1);  // + elu
    head2_kernel<<<(NN * 32 + 255) / 256, 256>>>(p_t1, Wc2, bc2, out);
}

// round 4
// speedup vs baseline: 2.0782x; 1.1085x over previous
#include <cuda_runtime.h>
#include <math.h>

#define NN 10000
#define EE 160000
#define ET (EE + NN)   // 170000 edges incl. self loops

// ---------------- scratch (device globals; no runtime allocation) ----------
__device__ float g_xl[(size_t)NN * 1024];
__device__ float g_xr[(size_t)NN * 1024];
__device__ float g_res[(size_t)NN * 1024];
__device__ float g_h1[(size_t)NN * 1024];
__device__ float g_h2[(size_t)NN * 128];
__device__ float g_h3[(size_t)NN * 128];
__device__ float g_t1[(size_t)NN * 64];
__device__ float g_e[(size_t)EE * 1024];     // per-edge transform (real edges)
__device__ float g_eself[1024];              // shared self-loop edge transform
__device__ float g_logit[(size_t)ET * 8];
__device__ float g_easum[32];
__device__ float g_meanea[32];
__device__ int   g_deg[NN];
__device__ int   g_off[NN + 1];
__device__ int   g_fill[NN];
__device__ int   g_csr[ET];

// ---------------- small setup kernels --------------------------------------
__global__ void zero_kernel() {
    int i = blockIdx.x * blockDim.x + threadIdx.x;
    if (i < NN) { g_deg[i] = 0; g_fill[i] = 0; }
    if (i < 32) g_easum[i] = 0.f;
}

__global__ void colsum_kernel(const float* __restrict__ ea) {
    int lane = threadIdx.x & 31;
    int warp = (blockIdx.x * blockDim.x + threadIdx.x) >> 5;
    int nwarp = (gridDim.x * blockDim.x) >> 5;
    float s = 0.f;
    for (int r = warp; r < EE; r += nwarp) s += ea[(size_t)r * 32 + lane];
    atomicAdd(&g_easum[lane], s);
}

__global__ void meanfin_kernel() {
    int c = threadIdx.x;
    if (c < 32) g_meanea[c] = g_easum[c] / (float)EE;
}

__global__ void hist_kernel(const int* __restrict__ ei) {
    int e = blockIdx.x * blockDim.x + threadIdx.x;
    if (e >= ET) return;
    int dst = (e < EE) ? ei[EE + e] : (e - EE);
    atomicAdd(&g_deg[dst], 1);
}

__global__ void scan_kernel() {
    __shared__ int s[1024];
    int t = threadIdx.x;
    const int CH = 10;  // 1024*10 >= NN
    int base = t * CH;
    int v[CH];
    int loc = 0;
#pragma unroll
    for (int i = 0; i < CH; i++) {
        int idx = base + i;
        v[i] = (idx < NN) ? g_deg[idx] : 0;
        loc += v[i];
    }
    s[t] = loc;
    __syncthreads();
    for (int o = 1; o < 1024; o <<= 1) {
        int x = (t >= o) ? s[t - o] : 0;
        __syncthreads();
        s[t] += x;
        __syncthreads();
    }
    int run = s[t] - loc;  // exclusive prefix for this chunk
#pragma unroll
    for (int i = 0; i < CH; i++) {
        int idx = base + i;
        if (idx < NN) g_off[idx] = run;
        run += v[i];
    }
    if (t == 1023) g_off[NN] = s[1023];
}

__global__ void scatter_kernel(const int* __restrict__ ei) {
    int e = blockIdx.x * blockDim.x + threadIdx.x;
    if (e >= ET) return;
    int dst = (e < EE) ? ei[EE + e] : (e - EE);
    int p = atomicAdd(&g_fill[dst], 1);
    g_csr[g_off[dst] + p] = e;
}

__global__ void eself_kernel(const float* __restrict__ We, int HC) {
    int c = blockIdx.x * blockDim.x + threadIdx.x;
    if (c >= HC) return;
    float s = 0.f;
#pragma unroll
    for (int k = 0; k < 32; k++) s += g_meanea[k] * We[(size_t)k * HC + c];
    g_eself[c] = s;
}

// ---------------- TF32 tensor-core GEMM (cp.async double-buffered) ---------
// C = A[MxK] @ B[KxN] (+bias)(+elu). K multiple of 16, N multiple of 16.
#define BM 128
#define BN 128
#define BK 16
#define AP 20    // A smem pitch (words): conflict-free for (m*20 + k) frag loads
#define BP 136   // B smem pitch (words): 136 % 32 == 8

__device__ __forceinline__ unsigned f2tf(float x) {
    unsigned r;
    asm("cvt.rna.tf32.f32 %0, %1;" : "=r"(r) : "f"(x));
    return r;
}

__device__ __forceinline__ void cp16(void* smem, const void* gmem, int src_bytes) {
    unsigned sa = (unsigned)__cvta_generic_to_shared(smem);
    asm volatile("cp.async.cg.shared.global [%0], [%1], 16, %2;\n"
                 :: "r"(sa), "l"(gmem), "r"(src_bytes));
}

__global__ __launch_bounds__(256, 2)
void gemm_tf32_kernel(const float* __restrict__ A, const float* __restrict__ B,
                      const float* __restrict__ bias, float* __restrict__ C,
                      int M, int N, int K, int act) {
    __shared__ float As[2][BM][AP];
    __shared__ float Bs[2][BK][BP];

    int tid = threadIdx.x;
    int warp = tid >> 5, lane = tid & 31;
    int wm = warp >> 2, wn = warp & 3;     // 2 x 4 warp grid; warp tile 64x32
    int gid = lane >> 2, tig = lane & 3;   // mma group id / thread-in-group
    int m0 = blockIdx.y * BM, n0 = blockIdx.x * BN;

    // A-tile copy slots: 512 chunks of 16B (128 rows x 4), 2 per thread
    int ac0 = tid, ac1 = tid + 256;
    // B-tile copy slots: 512 chunks (16 rows x 32), 2 per thread
    int bc0 = tid, bc1 = tid + 256;

    float acc[4][4][4];
#pragma unroll
    for (int mt = 0; mt < 4; mt++)
#pragma unroll
        for (int nt = 0; nt < 4; nt++)
#pragma unroll
            for (int i = 0; i < 4; i++) acc[mt][nt][i] = 0.f;

    int ntiles = K / BK;

    auto prefetch = [&](int t, int s) {
        int kt = t * BK;
        // A chunks
#pragma unroll
        for (int p = 0; p < 2; p++) {
            int c = p ? ac1 : ac0;
            int row = c >> 2, kc = (c & 3) * 4;
            int gr = m0 + row;
            int ok = (gr < M) ? 16 : 0;
            if (gr >= M) gr = M - 1;  // keep address in-range
            cp16(&As[s][row][kc], A + (size_t)gr * K + kt + kc, ok);
        }
        // B chunks
#pragma unroll
        for (int p = 0; p < 2; p++) {
            int c = p ? bc1 : bc0;
            int kr = c >> 5, nc = (c & 31) * 4;
            int gc = n0 + nc;
            int ok = (gc < N) ? 16 : 0;
            if (gc >= N) gc = N - 4;  // keep address in-range
            cp16(&Bs[s][kr][nc], B + (size_t)(kt + kr) * N + gc, ok);
        }
    };

    prefetch(0, 0);
    asm volatile("cp.async.commit_group;\n");

    for (int t = 0; t < ntiles; t++) {
        int s = t & 1;
        asm volatile("cp.async.wait_group 0;\n");
        __syncthreads();
        if (t + 1 < ntiles) prefetch(t + 1, s ^ 1);
        asm volatile("cp.async.commit_group;\n");

#pragma unroll
        for (int ks = 0; ks < 2; ks++) {
            int k0 = ks * 8;
            unsigned af[4][4], bf[4][2];
#pragma unroll
            for (int mt = 0; mt < 4; mt++) {
                int m = wm * 64 + mt * 16;
                af[mt][0] = f2tf(As[s][m + gid][k0 + tig]);
                af[mt][1] = f2tf(As[s][m + gid + 8][k0 + tig]);
                af[mt][2] = f2tf(As[s][m + gid][k0 + tig + 4]);
                af[mt][3] = f2tf(As[s][m + gid + 8][k0 + tig + 4]);
            }
#pragma unroll
            for (int nt = 0; nt < 4; nt++) {
                int n = wn * 32 + nt * 8;
                bf[nt][0] = f2tf(Bs[s][k0 + tig][n + gid]);
                bf[nt][1] = f2tf(Bs[s][k0 + tig + 4][n + gid]);
            }
#pragma unroll
            for (int mt = 0; mt < 4; mt++)
#pragma unroll
                for (int nt = 0; nt < 4; nt++) {
                    asm volatile(
                        "mma.sync.aligned.m16n8k8.row.col.f32.tf32.tf32.f32 "
                        "{%0,%1,%2,%3}, {%4,%5,%6,%7}, {%8,%9}, {%0,%1,%2,%3};"
                        : "+f"(acc[mt][nt][0]), "+f"(acc[mt][nt][1]),
                          "+f"(acc[mt][nt][2]), "+f"(acc[mt][nt][3])
                        : "r"(af[mt][0]), "r"(af[mt][1]), "r"(af[mt][2]), "r"(af[mt][3]),
                          "r"(bf[nt][0]), "r"(bf[nt][1]));
                }
        }
        __syncthreads();
    }

    // --- epilogue ---
#pragma unroll
    for (int mt = 0; mt < 4; mt++) {
        int rb = m0 + wm * 64 + mt * 16 + gid;
#pragma unroll
        for (int nt = 0; nt < 4; nt++) {
            int cb = n0 + wn * 32 + nt * 8 + tig * 2;
#pragma unroll
            for (int half = 0; half < 2; half++) {
                int r = rb + half * 8;
                if (r >= M) continue;
#pragma unroll
                for (int j = 0; j < 2; j++) {
                    int c = cb + j;
                    if (c >= N) continue;
                    float v = acc[mt][nt][half * 2 + j];
                    if (bias) v += bias[c];
                    if (act == 1) v = v > 0.f ? v : expm1f(v);  // ELU
                    C[(size_t)r * N + c] = v;
                }
            }
        }
    }
}

// ---------------- per-edge logits: one warp per edge -----------------------
template <int H>
__global__ void logits_kernel(const float* __restrict__ xl, const float* __restrict__ xr,
                              const float* __restrict__ eedge, const float* __restrict__ eself,
                              const float* __restrict__ att, const int* __restrict__ ei,
                              float* __restrict__ logit) {
    const int HC = H * 128;
    __shared__ float s_att[H * 128];
    for (int i = threadIdx.x; i < HC; i += blockDim.x) s_att[i] = att[i];
    __syncthreads();

    int gw = (blockIdx.x * blockDim.x + threadIdx.x) >> 5;
    int lane = threadIdx.x & 31;
    if (gw >= ET) return;
    int e = gw;
    int src = (e < EE) ? ei[e] : (e - EE);
    int dst = (e < EE) ? ei[EE + e] : (e - EE);
    const float4* pl = (const float4*)(xl + (size_t)src * HC);
    const float4* pr = (const float4*)(xr + (size_t)dst * HC);
    const float4* pe = (const float4*)((e < EE) ? (eedge + (size_t)e * HC) : eself);
    const float4* pa = (const float4*)s_att;

#pragma unroll
    for (int h = 0; h < H; h++) {
        int j = h * 32 + lane;
        float4 a = pl[j], b = pr[j], c = pe[j], w = pa[j];
        float u, p = 0.f;
        u = a.x + b.x + c.x; u = u > 0.f ? u : 0.2f * u; p += u * w.x;
        u = a.y + b.y + c.y; u = u > 0.f ? u : 0.2f * u; p += u * w.y;
        u = a.z + b.z + c.z; u = u > 0.f ? u : 0.2f * u; p += u * w.z;
        u = a.w + b.w + c.w; u = u > 0.f ? u : 0.2f * u; p += u * w.w;
#pragma unroll
        for (int o = 16; o; o >>= 1) p += __shfl_xor_sync(0xffffffffu, p, o);
        if (lane == 0) logit[(size_t)e * H + h] = p;
    }
}

// ---------------- node-parallel segment softmax + aggregation --------------
// ACT: 0 none, 1 leaky_relu(0.2), 2 elu
template <int H, int CONCAT, int ACT>
__global__ void agg_kernel(const float* __restrict__ xl, const float* __restrict__ logit,
                           const int* __restrict__ ei, const float* __restrict__ bias,
                           const float* __restrict__ res, float* __restrict__ out) {
    const int HC = H * 128;
    int n = blockIdx.x, t = threadIdx.x;  // 128 threads: t = channel-within-head
    int beg = g_off[n];
    int deg = g_off[n + 1] - beg;
    __shared__ float red[128];
    __shared__ float s_m[H], s_z[H];

    // phase 1: per-head max
    float lm[H];
#pragma unroll
    for (int h = 0; h < H; h++) lm[h] = -1e30f;
    for (int i = t; i < deg; i += 128) {
        int e = g_csr[beg + i];
#pragma unroll
        for (int h = 0; h < H; h++) lm[h] = fmaxf(lm[h], logit[(size_t)e * H + h]);
    }
#pragma unroll
    for (int h = 0; h < H; h++) {
        red[t] = lm[h];
        __syncthreads();
        for (int s = 64; s > 0; s >>= 1) {
            if (t < s) red[t] = fmaxf(red[t], red[t + s]);
            __syncthreads();
        }
        if (t == 0) s_m[h] = red[0];
        __syncthreads();
    }

    // phase 2: per-head denom
    float lz[H];
#pragma unroll
    for (int h = 0; h < H; h++) lz[h] = 0.f;
    for (int i = t; i < deg; i += 128) {
        int e = g_csr[beg + i];
#pragma unroll
        for (int h = 0; h < H; h++) lz[h] += __expf(logit[(size_t)e * H + h] - s_m[h]);
    }
#pragma unroll
    for (int h = 0; h < H; h++) {
        red[t] = lz[h];
        __syncthreads();
        for (int s = 64; s > 0; s >>= 1) {
            if (t < s) red[t] += red[t + s];
            __syncthreads();
        }
        if (t == 0) s_z[h] = red[0];
        __syncthreads();
    }

    // phase 3: weighted aggregation (all threads walk the edge list together)
    float acc[H];
#pragma unroll
    for (int h = 0; h < H; h++) acc[h] = 0.f;
    for (int i = 0; i < deg; i++) {
        int e = g_csr[beg + i];
        int src = (e < EE) ? ei[e] : (e - EE);
        const float* xp = xl + (size_t)src * HC;
#pragma unroll
        for (int h = 0; h < H; h++) {
            float w = __expf(logit[(size_t)e * H + h] - s_m[h]);
            acc[h] += w * xp[h * 128 + t];
        }
    }

    if (CONCAT) {
#pragma unroll
        for (int h = 0; h < H; h++) {
            float v = acc[h] / (s_z[h] + 1e-16f) + bias[h * 128 + t];
            if (res) v += res[(size_t)n * HC + h * 128 + t];
            if (ACT == 1) v = v > 0.f ? v : 0.2f * v;
            else if (ACT == 2) v = v > 0.f ? v : expm1f(v);
            out[(size_t)n * HC + h * 128 + t] = v;
        }
    } else {
        float v = 0.f;
#pragma unroll
        for (int h = 0; h < H; h++) v += acc[h] / (s_z[h] + 1e-16f);
        v = v * (1.f / H) + bias[t];
        if (ACT == 1) v = v > 0.f ? v : 0.2f * v;
        else if (ACT == 2) v = v > 0.f ? v : expm1f(v);
        out[(size_t)n * 128 + t] = v;
    }
}

// ---------------- final tiny GEMM [NN,64]x[64,3] ----------------------------
__global__ void head2_kernel(const float* __restrict__ t1, const float* __restrict__ W,
                             const float* __restrict__ b, float* __restrict__ out) {
    int gw = (blockIdx.x * blockDim.x + threadIdx.x) >> 5;
    int lane = threadIdx.x & 31;
    if (gw >= NN) return;
    float a0 = t1[(size_t)gw * 64 + lane];
    float a1 = t1[(size_t)gw * 64 + 32 + lane];
#pragma unroll
    for (int j = 0; j < 3; j++) {
        float p = a0 * W[lane * 3 + j] + a1 * W[(lane + 32) * 3 + j];
#pragma unroll
        for (int o = 16; o; o >>= 1) p += __shfl_xor_sync(0xffffffffu, p, o);
        if (lane == 0) out[(size_t)gw * 3 + j] = p + b[j];
    }
}

// ---------------- host orchestration ---------------------------------------
static inline void gemm(const float* A, const float* B, const float* bias, float* C,
                        int M, int N, int K, int act) {
    dim3 g((N + BN - 1) / BN, (M + BM - 1) / BM);
    gemm_tf32_kernel<<<g, 256>>>(A, B, bias, C, M, N, K, act);
}

extern "C" void kernel_launch(void* const* d_in, const int* in_sizes, int n_in,
                              void* d_out, int out_size) {
    const float* x    = (const float*)d_in[0];
    const int*   ei   = (const int*)d_in[1];
    const float* ea   = (const float*)d_in[2];
    const float* Wl1  = (const float*)d_in[3];
    const float* bl1  = (const float*)d_in[4];
    const float* Wr1  = (const float*)d_in[5];
    const float* br1  = (const float*)d_in[6];
    const float* We1  = (const float*)d_in[7];
    const float* att1 = (const float*)d_in[8];
    const float* bo1  = (const float*)d_in[9];
    const float* Wl2  = (const float*)d_in[10];
    const float* bl2  = (const float*)d_in[11];
    const float* Wr2  = (const float*)d_in[12];
    const float* br2  = (const float*)d_in[13];
    const float* We2  = (const float*)d_in[14];
    const float* att2 = (const float*)d_in[15];
    const float* bo2  = (const float*)d_in[16];
    const float* Wl3  = (const float*)d_in[17];
    const float* bl3  = (const float*)d_in[18];
    const float* Wr3  = (const float*)d_in[19];
    const float* br3  = (const float*)d_in[20];
    const float* We3  = (const float*)d_in[21];
    const float* att3 = (const float*)d_in[22];
    const float* bo3  = (const float*)d_in[23];
    const float* Wres = (const float*)d_in[24];
    const float* bres = (const float*)d_in[25];
    const float* Wc1  = (const float*)d_in[26];
    const float* bc1  = (const float*)d_in[27];
    const float* Wc2  = (const float*)d_in[28];
    const float* bc2  = (const float*)d_in[29];
    float* out = (float*)d_out;

    float *p_xl, *p_xr, *p_res, *p_h1, *p_h2, *p_h3, *p_t1, *p_e, *p_eself, *p_lg;
    cudaGetSymbolAddress((void**)&p_xl, g_xl);
    cudaGetSymbolAddress((void**)&p_xr, g_xr);
    cudaGetSymbolAddress((void**)&p_res, g_res);
    cudaGetSymbolAddress((void**)&p_h1, g_h1);
    cudaGetSymbolAddress((void**)&p_h2, g_h2);
    cudaGetSymbolAddress((void**)&p_h3, g_h3);
    cudaGetSymbolAddress((void**)&p_t1, g_t1);
    cudaGetSymbolAddress((void**)&p_e, g_e);
    cudaGetSymbolAddress((void**)&p_eself, g_eself);
    cudaGetSymbolAddress((void**)&p_lg, g_logit);

    // graph setup: mean edge attr + CSR by dst
    zero_kernel<<<(NN + 255) / 256, 256>>>();
    colsum_kernel<<<256, 256>>>(ea);
    hist_kernel<<<(ET + 255) / 256, 256>>>(ei);
    meanfin_kernel<<<1, 32>>>();
    scan_kernel<<<1, 1024>>>();
    scatter_kernel<<<(ET + 255) / 256, 256>>>(ei);

    const int LOG_GRID = (ET * 32 + 255) / 256;

    // ---- layer 1: H=8, C=128, concat; then +res, leaky_relu ----
    gemm(x, Wl1, bl1, p_xl, NN, 1024, 128, 0);
    gemm(x, Wr1, br1, p_xr, NN, 1024, 128, 0);
    gemm(x, Wres, bres, p_res, NN, 1024, 128, 0);
    gemm(ea, We1, nullptr, p_e, EE, 1024, 32, 0);
    eself_kernel<<<(1024 + 255) / 256, 256>>>(We1, 1024);
    logits_kernel<8><<<LOG_GRID, 256>>>(p_xl, p_xr, p_e, p_eself, att1, ei, p_lg);
    agg_kernel<8, 1, 1><<<NN, 128>>>(p_xl, p_lg, ei, bo1, p_res, p_h1);

    // ---- layer 2: H=4, C=128, mean; elu ----
    gemm(p_h1, Wl2, bl2, p_xl, NN, 512, 1024, 0);
    gemm(p_h1, Wr2, br2, p_xr, NN, 512, 1024, 0);
    gemm(ea, We2, nullptr, p_e, EE, 512, 32, 0);
    eself_kernel<<<(512 + 255) / 256, 256>>>(We2, 512);
    logits_kernel<4><<<LOG_GRID, 256>>>(p_xl, p_xr, p_e, p_eself, att2, ei, p_lg);
    agg_kernel<4, 0, 2><<<NN, 128>>>(p_xl, p_lg, ei, bo2, nullptr, p_h2);

    // ---- layer 3: H=1, C=128, concat; elu ----
    gemm(p_h2, Wl3, bl3, p_xl, NN, 128, 128, 0);
    gemm(p_h2, Wr3, br3, p_xr, NN, 128, 128, 0);
    gemm(ea, We3, nullptr, p_e, EE, 128, 32, 0);
    eself_kernel<<<1, 128>>>(We3, 128);
    logits_kernel<1><<<LOG_GRID, 256>>>(p_xl, p_xr, p_e, p_eself, att3, ei, p_lg);
    agg_kernel<1, 1, 2><<<NN, 128>>>(p_xl, p_lg, ei, bo3, nullptr, p_h3);

    // ---- head MLP ----
    gemm(p_h3, Wc1, bc1, p_t1, NN, 64, 128, 1);  // + elu
    head2_kernel<<<(NN * 32 + 255) / 256, 256>>>(p_t1, Wc2, bc2, out);
}

// round 5
// speedup vs baseline: 2.3328x; 1.1225x over previous
#include <cuda_runtime.h>
#include <math.h>

#define NN 10000
#define EE 160000
#define ET (EE + NN)   // 170000 edges incl. self loops

// ---------------- scratch (device globals; no runtime allocation) ----------
__device__ float g_xl[(size_t)NN * 1024];
__device__ float g_xr[(size_t)NN * 1024];
__device__ float g_res[(size_t)NN * 1024];
__device__ float g_h1[(size_t)NN * 1024];
__device__ float g_h2[(size_t)NN * 128];
__device__ float g_h3[(size_t)NN * 128];
__device__ float g_t1[(size_t)NN * 64];
__device__ float g_eself[1024];              // shared self-loop edge transform
__device__ float g_logit[(size_t)ET * 8];
__device__ float g_easum[32];
__device__ float g_meanea[32];
__device__ int   g_deg[NN];
__device__ int   g_off[NN + 1];
__device__ int   g_fill[NN];
__device__ int   g_csr[ET];

// ---------------- small setup kernels --------------------------------------
__global__ void zero_kernel() {
    int i = blockIdx.x * blockDim.x + threadIdx.x;
    if (i < NN) { g_deg[i] = 0; g_fill[i] = 0; }
    if (i < 32) g_easum[i] = 0.f;
}

__global__ void colsum_kernel(const float* __restrict__ ea) {
    int lane = threadIdx.x & 31;
    int warp = (blockIdx.x * blockDim.x + threadIdx.x) >> 5;
    int nwarp = (gridDim.x * blockDim.x) >> 5;
    float s = 0.f;
    for (int r = warp; r < EE; r += nwarp) s += ea[(size_t)r * 32 + lane];
    atomicAdd(&g_easum[lane], s);
}

__global__ void meanfin_kernel() {
    int c = threadIdx.x;
    if (c < 32) g_meanea[c] = g_easum[c] / (float)EE;
}

__global__ void hist_kernel(const int* __restrict__ ei) {
    int e = blockIdx.x * blockDim.x + threadIdx.x;
    if (e >= ET) return;
    int dst = (e < EE) ? ei[EE + e] : (e - EE);
    atomicAdd(&g_deg[dst], 1);
}

__global__ void scan_kernel() {
    __shared__ int s[1024];
    int t = threadIdx.x;
    const int CH = 10;  // 1024*10 >= NN
    int base = t * CH;
    int v[CH];
    int loc = 0;
#pragma unroll
    for (int i = 0; i < CH; i++) {
        int idx = base + i;
        v[i] = (idx < NN) ? g_deg[idx] : 0;
        loc += v[i];
    }
    s[t] = loc;
    __syncthreads();
    for (int o = 1; o < 1024; o <<= 1) {
        int x = (t >= o) ? s[t - o] : 0;
        __syncthreads();
        s[t] += x;
        __syncthreads();
    }
    int run = s[t] - loc;  // exclusive prefix for this chunk
#pragma unroll
    for (int i = 0; i < CH; i++) {
        int idx = base + i;
        if (idx < NN) g_off[idx] = run;
        run += v[i];
    }
    if (t == 1023) g_off[NN] = s[1023];
}

__global__ void scatter_kernel(const int* __restrict__ ei) {
    int e = blockIdx.x * blockDim.x + threadIdx.x;
    if (e >= ET) return;
    int dst = (e < EE) ? ei[EE + e] : (e - EE);
    int p = atomicAdd(&g_fill[dst], 1);
    g_csr[g_off[dst] + p] = e;
}

__global__ void eself_kernel(const float* __restrict__ We, int HC) {
    int c = blockIdx.x * blockDim.x + threadIdx.x;
    if (c >= HC) return;
    float s = 0.f;
#pragma unroll
    for (int k = 0; k < 32; k++) s += g_meanea[k] * We[(size_t)k * HC + c];
    g_eself[c] = s;
}

// ---------------- shared GEMM config ----------------------------------------
#define BM 128
#define BN 128
#define BK 16
#define AP 20    // A smem pitch (words)
#define BP 136   // B smem pitch (words)

__device__ __forceinline__ unsigned f2tf(float x) {
    unsigned r;
    asm("cvt.rna.tf32.f32 %0, %1;" : "=r"(r) : "f"(x));
    return r;
}

__device__ __forceinline__ void cp16(void* smem, const void* gmem, int src_bytes) {
    unsigned sa = (unsigned)__cvta_generic_to_shared(smem);
    asm volatile("cp.async.cg.shared.global [%0], [%1], 16, %2;\n"
                 :: "r"(sa), "l"(gmem), "r"(src_bytes));
}

#define MMA_TF32(acc, af, bf)                                                   \
    asm volatile(                                                               \
        "mma.sync.aligned.m16n8k8.row.col.f32.tf32.tf32.f32 "                   \
        "{%0,%1,%2,%3}, {%4,%5,%6,%7}, {%8,%9}, {%0,%1,%2,%3};"                 \
        : "+f"((acc)[0]), "+f"((acc)[1]), "+f"((acc)[2]), "+f"((acc)[3])        \
        : "r"((af)[0]), "r"((af)[1]), "r"((af)[2]), "r"((af)[3]),               \
          "r"((bf)[0]), "r"((bf)[1]))

// ---------------- TF32 tensor-core GEMM (cp.async double-buffered) ---------
// C = A[MxK] @ B[KxN] (+bias)(+elu). K multiple of 16, N multiple of 16.
__global__ __launch_bounds__(256, 2)
void gemm_tf32_kernel(const float* __restrict__ A, const float* __restrict__ B,
                      const float* __restrict__ bias, float* __restrict__ C,
                      int M, int N, int K, int act) {
    __shared__ float As[2][BM][AP];
    __shared__ float Bs[2][BK][BP];

    int tid = threadIdx.x;
    int warp = tid >> 5, lane = tid & 31;
    int wm = warp >> 2, wn = warp & 3;
    int gid = lane >> 2, tig = lane & 3;
    int m0 = blockIdx.y * BM, n0 = blockIdx.x * BN;

    int ac0 = tid, ac1 = tid + 256;
    int bc0 = tid, bc1 = tid + 256;

    float acc[4][4][4];
#pragma unroll
    for (int mt = 0; mt < 4; mt++)
#pragma unroll
        for (int nt = 0; nt < 4; nt++)
#pragma unroll
            for (int i = 0; i < 4; i++) acc[mt][nt][i] = 0.f;

    int ntiles = K / BK;

    auto prefetch = [&](int t, int s) {
        int kt = t * BK;
#pragma unroll
        for (int p = 0; p < 2; p++) {
            int c = p ? ac1 : ac0;
            int row = c >> 2, kc = (c & 3) * 4;
            int gr = m0 + row;
            int ok = (gr < M) ? 16 : 0;
            if (gr >= M) gr = M - 1;
            cp16(&As[s][row][kc], A + (size_t)gr * K + kt + kc, ok);
        }
#pragma unroll
        for (int p = 0; p < 2; p++) {
            int c = p ? bc1 : bc0;
            int kr = c >> 5, nc = (c & 31) * 4;
            int gc = n0 + nc;
            int ok = (gc < N) ? 16 : 0;
            if (gc >= N) gc = N - 4;
            cp16(&Bs[s][kr][nc], B + (size_t)(kt + kr) * N + gc, ok);
        }
    };

    prefetch(0, 0);
    asm volatile("cp.async.commit_group;\n");

    for (int t = 0; t < ntiles; t++) {
        int s = t & 1;
        asm volatile("cp.async.wait_group 0;\n");
        __syncthreads();
        if (t + 1 < ntiles) prefetch(t + 1, s ^ 1);
        asm volatile("cp.async.commit_group;\n");

#pragma unroll
        for (int ks = 0; ks < 2; ks++) {
            int k0 = ks * 8;
            unsigned af[4][4], bf[4][2];
#pragma unroll
            for (int mt = 0; mt < 4; mt++) {
                int m = wm * 64 + mt * 16;
                af[mt][0] = f2tf(As[s][m + gid][k0 + tig]);
                af[mt][1] = f2tf(As[s][m + gid + 8][k0 + tig]);
                af[mt][2] = f2tf(As[s][m + gid][k0 + tig + 4]);
                af[mt][3] = f2tf(As[s][m + gid + 8][k0 + tig + 4]);
            }
#pragma unroll
            for (int nt = 0; nt < 4; nt++) {
                int n = wn * 32 + nt * 8;
                bf[nt][0] = f2tf(Bs[s][k0 + tig][n + gid]);
                bf[nt][1] = f2tf(Bs[s][k0 + tig + 4][n + gid]);
            }
#pragma unroll
            for (int mt = 0; mt < 4; mt++)
#pragma unroll
                for (int nt = 0; nt < 4; nt++) MMA_TF32(acc[mt][nt], af[mt], bf[nt]);
        }
        __syncthreads();
    }

#pragma unroll
    for (int mt = 0; mt < 4; mt++) {
        int rb = m0 + wm * 64 + mt * 16 + gid;
#pragma unroll
        for (int nt = 0; nt < 4; nt++) {
            int cb = n0 + wn * 32 + nt * 8 + tig * 2;
#pragma unroll
            for (int half = 0; half < 2; half++) {
                int r = rb + half * 8;
                if (r >= M) continue;
#pragma unroll
                for (int j = 0; j < 2; j++) {
                    int c = cb + j;
                    if (c >= N) continue;
                    float v = acc[mt][nt][half * 2 + j];
                    if (bias) v += bias[c];
                    if (act == 1) v = v > 0.f ? v : expm1f(v);  // ELU
                    C[(size_t)r * N + c] = v;
                }
            }
        }
    }
}

// ---------------- fused edge-transform GEMM + logits ------------------------
// A = ea [EE x 32], B = We [32 x N], N = H*128. Block's 128 columns == one head.
// Instead of writing e to gmem, stage the tile in smem and compute
// logit[e][head] = sum_c leakyrelu(e + xl[src] + xr[dst])_c * att_c  directly.
__global__ __launch_bounds__(256, 2)
void gemm_logits_kernel(const float* __restrict__ A, const float* __restrict__ B,
                        const float* __restrict__ xl, const float* __restrict__ xr,
                        const float* __restrict__ att, const int* __restrict__ ei,
                        float* __restrict__ logit, int N, int H) {
    const int K = 32;                       // edge-attr dim
    __shared__ __align__(16) float pool[2 * BM * AP + 2 * BK * BP];  // 9472 words
    float (*As)[BM][AP] = (float(*)[BM][AP])pool;
    float (*Bs)[BK][BP] = (float(*)[BK][BP])(pool + 2 * BM * AP);
    __shared__ float s_att[128];

    int tid = threadIdx.x;
    int warp = tid >> 5, lane = tid & 31;
    int wm = warp >> 2, wn = warp & 3;
    int gid = lane >> 2, tig = lane & 3;
    int m0 = blockIdx.y * BM, n0 = blockIdx.x * BN;
    int head = n0 >> 7;

    if (tid < 128) s_att[tid] = att[head * 128 + tid];

    int ac0 = tid, ac1 = tid + 256;
    int bc0 = tid, bc1 = tid + 256;

    float acc[4][4][4];
#pragma unroll
    for (int mt = 0; mt < 4; mt++)
#pragma unroll
        for (int nt = 0; nt < 4; nt++)
#pragma unroll
            for (int i = 0; i < 4; i++) acc[mt][nt][i] = 0.f;

    auto prefetch = [&](int t, int s) {
        int kt = t * BK;
#pragma unroll
        for (int p = 0; p < 2; p++) {
            int c = p ? ac1 : ac0;
            int row = c >> 2, kc = (c & 3) * 4;
            cp16(&(*As)[row][kc] + s * 0, A + (size_t)(m0 + row) * K + kt + kc, 16);
            // note: buffer select via explicit index below instead
        }
    };
    (void)prefetch;  // replaced by explicit code (buffer indexing)

    // explicit prefetch (buffer s)
    auto pf = [&](int t, int s) {
        int kt = t * BK;
#pragma unroll
        for (int p = 0; p < 2; p++) {
            int c = p ? ac1 : ac0;
            int row = c >> 2, kc = (c & 3) * 4;
            cp16(&As[s][row][kc], A + (size_t)(m0 + row) * K + kt + kc, 16);
        }
#pragma unroll
        for (int p = 0; p < 2; p++) {
            int c = p ? bc1 : bc0;
            int kr = c >> 5, nc = (c & 31) * 4;
            cp16(&Bs[s][kr][nc], B + (size_t)(kt + kr) * N + n0 + nc, 16);
        }
    };

    pf(0, 0);
    asm volatile("cp.async.commit_group;\n");

    const int ntiles = K / BK;  // 2
#pragma unroll
    for (int t = 0; t < ntiles; t++) {
        int s = t & 1;
        asm volatile("cp.async.wait_group 0;\n");
        __syncthreads();
        if (t + 1 < ntiles) pf(t + 1, s ^ 1);
        asm volatile("cp.async.commit_group;\n");

#pragma unroll
        for (int ks = 0; ks < 2; ks++) {
            int k0 = ks * 8;
            unsigned af[4][4], bf[4][2];
#pragma unroll
            for (int mt = 0; mt < 4; mt++) {
                int m = wm * 64 + mt * 16;
                af[mt][0] = f2tf(As[s][m + gid][k0 + tig]);
                af[mt][1] = f2tf(As[s][m + gid + 8][k0 + tig]);
                af[mt][2] = f2tf(As[s][m + gid][k0 + tig + 4]);
                af[mt][3] = f2tf(As[s][m + gid + 8][k0 + tig + 4]);
            }
#pragma unroll
            for (int nt = 0; nt < 4; nt++) {
                int n = wn * 32 + nt * 8;
                bf[nt][0] = f2tf(Bs[s][k0 + tig][n + gid]);
                bf[nt][1] = f2tf(Bs[s][k0 + tig + 4][n + gid]);
            }
#pragma unroll
            for (int mt = 0; mt < 4; mt++)
#pragma unroll
                for (int nt = 0; nt < 4; nt++) MMA_TF32(acc[mt][nt], af[mt], bf[nt]);
        }
        __syncthreads();
    }

    // --- fused logits epilogue: 2 passes of 64 edges, smem aliased over pool ---
    float (*Cs)[BN + 4] = (float(*)[BN + 4])pool;  // 64 x 132 = 8448 <= 9472
#pragma unroll
    for (int pass = 0; pass < 2; pass++) {
        __syncthreads();  // prior pass reads / mainloop done before overwrite
        if (wm == pass) {
#pragma unroll
            for (int mt = 0; mt < 4; mt++)
#pragma unroll
                for (int nt = 0; nt < 4; nt++) {
                    int cb = wn * 32 + nt * 8 + tig * 2;
#pragma unroll
                    for (int half = 0; half < 2; half++) {
                        int lr = mt * 16 + gid + half * 8;
                        Cs[lr][cb + 0] = acc[mt][nt][half * 2 + 0];
                        Cs[lr][cb + 1] = acc[mt][nt][half * 2 + 1];
                    }
                }
        }
        __syncthreads();

        float4 w = *(const float4*)&s_att[lane * 4];
        for (int eo = warp; eo < 64; eo += 8) {
            int ed = m0 + pass * 64 + eo;
            int src = ei[ed];
            int dst = ei[EE + ed];
            float4 ev = *(const float4*)&Cs[eo][lane * 4];
            float4 a = *(const float4*)(xl + (size_t)src * N + n0 + lane * 4);
            float4 b = *(const float4*)(xr + (size_t)dst * N + n0 + lane * 4);
            float u, p = 0.f;
            u = a.x + b.x + ev.x; u = u > 0.f ? u : 0.2f * u; p += u * w.x;
            u = a.y + b.y + ev.y; u = u > 0.f ? u : 0.2f * u; p += u * w.y;
            u = a.z + b.z + ev.z; u = u > 0.f ? u : 0.2f * u; p += u * w.z;
            u = a.w + b.w + ev.w; u = u > 0.f ? u : 0.2f * u; p += u * w.w;
#pragma unroll
            for (int o = 16; o; o >>= 1) p += __shfl_xor_sync(0xffffffffu, p, o);
            if (lane == 0) logit[(size_t)ed * H + head] = p;
        }
    }
}

// ---------------- self-loop logits: one warp per node -----------------------
template <int H>
__global__ void selflogits_kernel(const float* __restrict__ xl, const float* __restrict__ xr,
                                  const float* __restrict__ eself, const float* __restrict__ att,
                                  float* __restrict__ logit) {
    const int HC = H * 128;
    __shared__ float s_att[H * 128];
    for (int i = threadIdx.x; i < HC; i += blockDim.x) s_att[i] = att[i];
    __syncthreads();

    int n = (blockIdx.x * blockDim.x + threadIdx.x) >> 5;
    int lane = threadIdx.x & 31;
    if (n >= NN) return;
    const float4* pl = (const float4*)(xl + (size_t)n * HC);
    const float4* pr = (const float4*)(xr + (size_t)n * HC);
    const float4* pe = (const float4*)eself;
    const float4* pa = (const float4*)s_att;

#pragma unroll
    for (int h = 0; h < H; h++) {
        int j = h * 32 + lane;
        float4 a = pl[j], b = pr[j], c = pe[j], w = pa[j];
        float u, p = 0.f;
        u = a.x + b.x + c.x; u = u > 0.f ? u : 0.2f * u; p += u * w.x;
        u = a.y + b.y + c.y; u = u > 0.f ? u : 0.2f * u; p += u * w.y;
        u = a.z + b.z + c.z; u = u > 0.f ? u : 0.2f * u; p += u * w.z;
        u = a.w + b.w + c.w; u = u > 0.f ? u : 0.2f * u; p += u * w.w;
#pragma unroll
        for (int o = 16; o; o >>= 1) p += __shfl_xor_sync(0xffffffffu, p, o);
        if (lane == 0) logit[(size_t)(EE + n) * H + h] = p;
    }
}

// ---------------- node-parallel segment softmax + aggregation --------------
// ACT: 0 none, 1 leaky_relu(0.2), 2 elu
template <int H, int CONCAT, int ACT>
__global__ void agg_kernel(const float* __restrict__ xl, const float* __restrict__ logit,
                           const int* __restrict__ ei, const float* __restrict__ bias,
                           const float* __restrict__ res, float* __restrict__ out) {
    const int HC = H * 128;
    int n = blockIdx.x, t = threadIdx.x;
    int beg = g_off[n];
    int deg = g_off[n + 1] - beg;
    __shared__ float red[128];
    __shared__ float s_m[H], s_z[H];

    float lm[H];
#pragma unroll
    for (int h = 0; h < H; h++) lm[h] = -1e30f;
    for (int i = t; i < deg; i += 128) {
        int e = g_csr[beg + i];
#pragma unroll
        for (int h = 0; h < H; h++) lm[h] = fmaxf(lm[h], logit[(size_t)e * H + h]);
    }
#pragma unroll
    for (int h = 0; h < H; h++) {
        red[t] = lm[h];
        __syncthreads();
        for (int s = 64; s > 0; s >>= 1) {
            if (t < s) red[t] = fmaxf(red[t], red[t + s]);
            __syncthreads();
        }
        if (t == 0) s_m[h] = red[0];
        __syncthreads();
    }

    float lz[H];
#pragma unroll
    for (int h = 0; h < H; h++) lz[h] = 0.f;
    for (int i = t; i < deg; i += 128) {
        int e = g_csr[beg + i];
#pragma unroll
        for (int h = 0; h < H; h++) lz[h] += __expf(logit[(size_t)e * H + h] - s_m[h]);
    }
#pragma unroll
    for (int h = 0; h < H; h++) {
        red[t] = lz[h];
        __syncthreads();
        for (int s = 64; s > 0; s >>= 1) {
            if (t < s) red[t] += red[t + s];
            __syncthreads();
        }
        if (t == 0) s_z[h] = red[0];
        __syncthreads();
    }

    float acc[H];
#pragma unroll
    for (int h = 0; h < H; h++) acc[h] = 0.f;
    for (int i = 0; i < deg; i++) {
        int e = g_csr[beg + i];
        int src = (e < EE) ? ei[e] : (e - EE);
        const float* xp = xl + (size_t)src * HC;
#pragma unroll
        for (int h = 0; h < H; h++) {
            float w = __expf(logit[(size_t)e * H + h] - s_m[h]);
            acc[h] += w * xp[h * 128 + t];
        }
    }

    if (CONCAT) {
#pragma unroll
        for (int h = 0; h < H; h++) {
            float v = acc[h] / (s_z[h] + 1e-16f) + bias[h * 128 + t];
            if (res) v += res[(size_t)n * HC + h * 128 + t];
            if (ACT == 1) v = v > 0.f ? v : 0.2f * v;
            else if (ACT == 2) v = v > 0.f ? v : expm1f(v);
            out[(size_t)n * HC + h * 128 + t] = v;
        }
    } else {
        float v = 0.f;
#pragma unroll
        for (int h = 0; h < H; h++) v += acc[h] / (s_z[h] + 1e-16f);
        v = v * (1.f / H) + bias[t];
        if (ACT == 1) v = v > 0.f ? v : 0.2f * v;
        else if (ACT == 2) v = v > 0.f ? v : expm1f(v);
        out[(size_t)n * 128 + t] = v;
    }
}

// ---------------- final tiny GEMM [NN,64]x[64,3] ----------------------------
__global__ void head2_kernel(const float* __restrict__ t1, const float* __restrict__ W,
                             const float* __restrict__ b, float* __restrict__ out) {
    int gw = (blockIdx.x * blockDim.x + threadIdx.x) >> 5;
    int lane = threadIdx.x & 31;
    if (gw >= NN) return;
    float a0 = t1[(size_t)gw * 64 + lane];
    float a1 = t1[(size_t)gw * 64 + 32 + lane];
#pragma unroll
    for (int j = 0; j < 3; j++) {
        float p = a0 * W[lane * 3 + j] + a1 * W[(lane + 32) * 3 + j];
#pragma unroll
        for (int o = 16; o; o >>= 1) p += __shfl_xor_sync(0xffffffffu, p, o);
        if (lane == 0) out[(size_t)gw * 3 + j] = p + b[j];
    }
}

// ---------------- host orchestration ---------------------------------------
static inline void gemm(const float* A, const float* B, const float* bias, float* C,
                        int M, int N, int K, int act) {
    dim3 g((N + BN - 1) / BN, (M + BM - 1) / BM);
    gemm_tf32_kernel<<<g, 256>>>(A, B, bias, C, M, N, K, act);
}

extern "C" void kernel_launch(void* const* d_in, const int* in_sizes, int n_in,
                              void* d_out, int out_size) {
    const float* x    = (const float*)d_in[0];
    const int*   ei   = (const int*)d_in[1];
    const float* ea   = (const float*)d_in[2];
    const float* Wl1  = (const float*)d_in[3];
    const float* bl1  = (const float*)d_in[4];
    const float* Wr1  = (const float*)d_in[5];
    const float* br1  = (const float*)d_in[6];
    const float* We1  = (const float*)d_in[7];
    const float* att1 = (const float*)d_in[8];
    const float* bo1  = (const float*)d_in[9];
    const float* Wl2  = (const float*)d_in[10];
    const float* bl2  = (const float*)d_in[11];
    const float* Wr2  = (const float*)d_in[12];
    const float* br2  = (const float*)d_in[13];
    const float* We2  = (const float*)d_in[14];
    const float* att2 = (const float*)d_in[15];
    const float* bo2  = (const float*)d_in[16];
    const float* Wl3  = (const float*)d_in[17];
    const float* bl3  = (const float*)d_in[18];
    const float* Wr3  = (const float*)d_in[19];
    const float* br3  = (const float*)d_in[20];
    const float* We3  = (const float*)d_in[21];
    const float* att3 = (const float*)d_in[22];
    const float* bo3  = (const float*)d_in[23];
    const float* Wres = (const float*)d_in[24];
    const float* bres = (const float*)d_in[25];
    const float* Wc1  = (const float*)d_in[26];
    const float* bc1  = (const float*)d_in[27];
    const float* Wc2  = (const float*)d_in[28];
    const float* bc2  = (const float*)d_in[29];
    float* out = (float*)d_out;

    float *p_xl, *p_xr, *p_res, *p_h1, *p_h2, *p_h3, *p_t1, *p_eself, *p_lg;
    cudaGetSymbolAddress((void**)&p_xl, g_xl);
    cudaGetSymbolAddress((void**)&p_xr, g_xr);
    cudaGetSymbolAddress((void**)&p_res, g_res);
    cudaGetSymbolAddress((void**)&p_h1, g_h1);
    cudaGetSymbolAddress((void**)&p_h2, g_h2);
    cudaGetSymbolAddress((void**)&p_h3, g_h3);
    cudaGetSymbolAddress((void**)&p_t1, g_t1);
    cudaGetSymbolAddress((void**)&p_eself, g_eself);
    cudaGetSymbolAddress((void**)&p_lg, g_logit);

    // graph setup: mean edge attr + CSR by dst
    zero_kernel<<<(NN + 255) / 256, 256>>>();
    colsum_kernel<<<256, 256>>>(ea);
    hist_kernel<<<(ET + 255) / 256, 256>>>(ei);
    meanfin_kernel<<<1, 32>>>();
    scan_kernel<<<1, 1024>>>();
    scatter_kernel<<<(ET + 255) / 256, 256>>>(ei);

    const int SELF_GRID = (NN * 32 + 255) / 256;

    // ---- layer 1: H=8, C=128, concat; then +res, leaky_relu ----
    gemm(x, Wl1, bl1, p_xl, NN, 1024, 128, 0);
    gemm(x, Wr1, br1, p_xr, NN, 1024, 128, 0);
    gemm(x, Wres, bres, p_res, NN, 1024, 128, 0);
    eself_kernel<<<(1024 + 255) / 256, 256>>>(We1, 1024);
    {
        dim3 ge(1024 / BN, EE / BM);
        gemm_logits_kernel<<<ge, 256>>>(ea, We1, p_xl, p_xr, att1, ei, p_lg, 1024, 8);
    }
    selflogits_kernel<8><<<SELF_GRID, 256>>>(p_xl, p_xr, p_eself, att1, p_lg);
    agg_kernel<8, 1, 1><<<NN, 128>>>(p_xl, p_lg, ei, bo1, p_res, p_h1);

    // ---- layer 2: H=4, C=128, mean; elu ----
    gemm(p_h1, Wl2, bl2, p_xl, NN, 512, 1024, 0);
    gemm(p_h1, Wr2, br2, p_xr, NN, 512, 1024, 0);
    eself_kernel<<<(512 + 255) / 256, 256>>>(We2, 512);
    {
        dim3 ge(512 / BN, EE / BM);
        gemm_logits_kernel<<<ge, 256>>>(ea, We2, p_xl, p_xr, att2, ei, p_lg, 512, 4);
    }
    selflogits_kernel<4><<<SELF_GRID, 256>>>(p_xl, p_xr, p_eself, att2, p_lg);
    agg_kernel<4, 0, 2><<<NN, 128>>>(p_xl, p_lg, ei, bo2, nullptr, p_h2);

    // ---- layer 3: H=1, C=128, concat; elu ----
    gemm(p_h2, Wl3, bl3, p_xl, NN, 128, 128, 0);
    gemm(p_h2, Wr3, br3, p_xr, NN, 128, 128, 0);
    eself_kernel<<<1, 128>>>(We3, 128);
    {
        dim3 ge(128 / BN, EE / BM);
        gemm_logits_kernel<<<ge, 256>>>(ea, We3, p_xl, p_xr, att3, ei, p_lg, 128, 1);
    }
    selflogits_kernel<1><<<SELF_GRID, 256>>>(p_xl, p_xr, p_eself, att3, p_lg);
    agg_kernel<1, 1, 2><<<NN, 128>>>(p_xl, p_lg, ei, bo3, nullptr, p_h3);

    // ---- head MLP ----
    gemm(p_h3, Wc1, bc1, p_t1, NN, 64, 128, 1);  // + elu
    head2_kernel<<<(NN * 32 + 255) / 256, 256>>>(p_t1, Wc2, bc2, out);
}

// round 6
// speedup vs baseline: 2.4569x; 1.0532x over previous
#include <cuda_runtime.h>
#include <math.h>

#define NN 10000
#define EE 160000
#define ET (EE + NN)   // 170000 edges incl. self loops

// ---------------- scratch (device globals; no runtime allocation) ----------
__device__ float g_big[(size_t)NN * 3072];   // packed xl|xr|res per layer
__device__ float g_h1[(size_t)NN * 1024];
__device__ float g_h2[(size_t)NN * 128];
__device__ float g_h3[(size_t)NN * 128];
__device__ float g_t1[(size_t)NN * 64];
__device__ float g_wcat[1024 * 1024];        // packed weight scratch (4 MB)
__device__ float g_bcat[3072];
__device__ float g_eself[1024];              // shared self-loop edge transform
__device__ float g_logit[(size_t)ET * 8];
__device__ float g_easum[32];
__device__ float g_meanea[32];
__device__ int   g_deg[NN];
__device__ int   g_off[NN + 1];
__device__ int   g_fill[NN];
__device__ int   g_csr[ET];

// ---------------- small setup kernels --------------------------------------
__global__ void zero_kernel() {
    int i = blockIdx.x * blockDim.x + threadIdx.x;
    if (i < NN) { g_deg[i] = 0; g_fill[i] = 0; }
    if (i < 32) g_easum[i] = 0.f;
}

__global__ void colsum_kernel(const float* __restrict__ ea) {
    int lane = threadIdx.x & 31;
    int warp = (blockIdx.x * blockDim.x + threadIdx.x) >> 5;
    int nwarp = (gridDim.x * blockDim.x) >> 5;
    float s = 0.f;
    for (int r = warp; r < EE; r += nwarp) s += ea[(size_t)r * 32 + lane];
    atomicAdd(&g_easum[lane], s);
}

__global__ void meanfin_kernel() {
    int c = threadIdx.x;
    if (c < 32) g_meanea[c] = g_easum[c] / (float)EE;
}

__global__ void hist_kernel(const int* __restrict__ ei) {
    int e = blockIdx.x * blockDim.x + threadIdx.x;
    if (e >= ET) return;
    int dst = (e < EE) ? ei[EE + e] : (e - EE);
    atomicAdd(&g_deg[dst], 1);
}

__global__ void scan_kernel() {
    __shared__ int s[1024];
    int t = threadIdx.x;
    const int CH = 10;  // 1024*10 >= NN
    int base = t * CH;
    int v[CH];
    int loc = 0;
#pragma unroll
    for (int i = 0; i < CH; i++) {
        int idx = base + i;
        v[i] = (idx < NN) ? g_deg[idx] : 0;
        loc += v[i];
    }
    s[t] = loc;
    __syncthreads();
    for (int o = 1; o < 1024; o <<= 1) {
        int x = (t >= o) ? s[t - o] : 0;
        __syncthreads();
        s[t] += x;
        __syncthreads();
    }
    int run = s[t] - loc;
#pragma unroll
    for (int i = 0; i < CH; i++) {
        int idx = base + i;
        if (idx < NN) g_off[idx] = run;
        run += v[i];
    }
    if (t == 1023) g_off[NN] = s[1023];
}

__global__ void scatter_kernel(const int* __restrict__ ei) {
    int e = blockIdx.x * blockDim.x + threadIdx.x;
    if (e >= ET) return;
    int dst = (e < EE) ? ei[EE + e] : (e - EE);
    int p = atomicAdd(&g_fill[dst], 1);
    g_csr[g_off[dst] + p] = e;
}

__global__ void eself_kernel(const float* __restrict__ We, int HC) {
    int c = blockIdx.x * blockDim.x + threadIdx.x;
    if (c >= HC) return;
    float s = 0.f;
#pragma unroll
    for (int k = 0; k < 32; k++) s += g_meanea[k] * We[(size_t)k * HC + c];
    g_eself[c] = s;
}

// ---------------- shared GEMM config ----------------------------------------
#define BM 128
#define BN 128
#define BK 16     // for the fused edge/logits kernel (K=32)
#define AP 20
#define BP 136
#define BK2 32    // for the main node GEMM
#define AP2 36    // A pitch for BK2 (conflict-free: 36*gid%32 = 4*gid)
#define GSMEM ((2 * BM * AP2 + 2 * BK2 * BP) * 4)   // 71680 bytes

__device__ __forceinline__ unsigned f2tf(float x) {
    unsigned r;
    asm("cvt.rna.tf32.f32 %0, %1;" : "=r"(r) : "f"(x));
    return r;
}

__device__ __forceinline__ void cp16(void* smem, const void* gmem, int src_bytes) {
    unsigned sa = (unsigned)__cvta_generic_to_shared(smem);
    asm volatile("cp.async.cg.shared.global [%0], [%1], 16, %2;\n"
                 :: "r"(sa), "l"(gmem), "r"(src_bytes));
}

#define MMA_TF32(acc, af, bf)                                                   \
    asm volatile(                                                               \
        "mma.sync.aligned.m16n8k8.row.col.f32.tf32.tf32.f32 "                   \
        "{%0,%1,%2,%3}, {%4,%5,%6,%7}, {%8,%9}, {%0,%1,%2,%3};"                 \
        : "+f"((acc)[0]), "+f"((acc)[1]), "+f"((acc)[2]), "+f"((acc)[3])        \
        : "r"((af)[0]), "r"((af)[1]), "r"((af)[2]), "r"((af)[3]),               \
          "r"((bf)[0]), "r"((bf)[1]))

// ---------------- TF32 node GEMM: BK=32, dynamic smem, double-buffered ------
// C = A[MxK] @ B[KxN] (+bias)(+elu). K multiple of 32.
__global__ __launch_bounds__(256, 2)
void gemm_tf32_kernel(const float* __restrict__ A, const float* __restrict__ B,
                      const float* __restrict__ bias, float* __restrict__ C,
                      int M, int N, int K, int act) {
    extern __shared__ float pool[];
    float (*As)[BM][AP2] = (float(*)[BM][AP2])pool;
    float (*Bs)[BK2][BP] = (float(*)[BK2][BP])(pool + 2 * BM * AP2);

    int tid = threadIdx.x;
    int warp = tid >> 5, lane = tid & 31;
    int wm = warp >> 2, wn = warp & 3;
    int gid = lane >> 2, tig = lane & 3;
    int m0 = blockIdx.y * BM, n0 = blockIdx.x * BN;

    float acc[4][4][4];
#pragma unroll
    for (int mt = 0; mt < 4; mt++)
#pragma unroll
        for (int nt = 0; nt < 4; nt++)
#pragma unroll
            for (int i = 0; i < 4; i++) acc[mt][nt][i] = 0.f;

    int ntiles = K / BK2;

    auto prefetch = [&](int t, int s) {
        int kt = t * BK2;
        // A: 128 x 32 = 1024 float4 chunks
#pragma unroll
        for (int p = 0; p < 4; p++) {
            int c = tid + p * 256;
            int row = c >> 3, kc = (c & 7) * 4;
            int gr = m0 + row;
            int ok = (gr < M) ? 16 : 0;
            if (gr >= M) gr = M - 1;
            cp16(&As[s][row][kc], A + (size_t)gr * K + kt + kc, ok);
        }
        // B: 32 x 128 = 1024 chunks
#pragma unroll
        for (int p = 0; p < 4; p++) {
            int c = tid + p * 256;
            int kr = c >> 5, nc = (c & 31) * 4;
            int gc = n0 + nc;
            int ok = (gc < N) ? 16 : 0;
            if (gc >= N) gc = N - 4;
            cp16(&Bs[s][kr][nc], B + (size_t)(kt + kr) * N + gc, ok);
        }
    };

    prefetch(0, 0);
    asm volatile("cp.async.commit_group;\n");

    for (int t = 0; t < ntiles; t++) {
        int s = t & 1;
        asm volatile("cp.async.wait_group 0;\n");
        __syncthreads();
        if (t + 1 < ntiles) prefetch(t + 1, s ^ 1);
        asm volatile("cp.async.commit_group;\n");

#pragma unroll
        for (int ks = 0; ks < 4; ks++) {
            int k0 = ks * 8;
            unsigned af[4][4], bf[4][2];
#pragma unroll
            for (int mt = 0; mt < 4; mt++) {
                int m = wm * 64 + mt * 16;
                af[mt][0] = f2tf(As[s][m + gid][k0 + tig]);
                af[mt][1] = f2tf(As[s][m + gid + 8][k0 + tig]);
                af[mt][2] = f2tf(As[s][m + gid][k0 + tig + 4]);
                af[mt][3] = f2tf(As[s][m + gid + 8][k0 + tig + 4]);
            }
#pragma unroll
            for (int nt = 0; nt < 4; nt++) {
                int n = wn * 32 + nt * 8;
                bf[nt][0] = f2tf(Bs[s][k0 + tig][n + gid]);
                bf[nt][1] = f2tf(Bs[s][k0 + tig + 4][n + gid]);
            }
#pragma unroll
            for (int mt = 0; mt < 4; mt++)
#pragma unroll
                for (int nt = 0; nt < 4; nt++) MMA_TF32(acc[mt][nt], af[mt], bf[nt]);
        }
        __syncthreads();
    }

#pragma unroll
    for (int mt = 0; mt < 4; mt++) {
        int rb = m0 + wm * 64 + mt * 16 + gid;
#pragma unroll
        for (int nt = 0; nt < 4; nt++) {
            int cb = n0 + wn * 32 + nt * 8 + tig * 2;
#pragma unroll
            for (int half = 0; half < 2; half++) {
                int r = rb + half * 8;
                if (r >= M) continue;
#pragma unroll
                for (int j = 0; j < 2; j++) {
                    int c = cb + j;
                    if (c >= N) continue;
                    float v = acc[mt][nt][half * 2 + j];
                    if (bias) v += bias[c];
                    if (act == 1) v = v > 0.f ? v : expm1f(v);  // ELU
                    C[(size_t)r * N + c] = v;
                }
            }
        }
    }
}

// ---------------- fused edge-transform GEMM + logits (K=32, BK=16) ----------
__global__ __launch_bounds__(256, 2)
void gemm_logits_kernel(const float* __restrict__ A, const float* __restrict__ B,
                        const float* __restrict__ xl, const float* __restrict__ xr,
                        int xls, const float* __restrict__ att,
                        const int* __restrict__ ei, float* __restrict__ logit,
                        int N, int H) {
    const int K = 32;
    __shared__ __align__(16) float pool[2 * BM * AP + 2 * BK * BP];
    float (*As)[BM][AP] = (float(*)[BM][AP])pool;
    float (*Bs)[BK][BP] = (float(*)[BK][BP])(pool + 2 * BM * AP);
    __shared__ float s_att[128];

    int tid = threadIdx.x;
    int warp = tid >> 5, lane = tid & 31;
    int wm = warp >> 2, wn = warp & 3;
    int gid = lane >> 2, tig = lane & 3;
    int m0 = blockIdx.y * BM, n0 = blockIdx.x * BN;
    int head = n0 >> 7;

    if (tid < 128) s_att[tid] = att[head * 128 + tid];

    int ac0 = tid, ac1 = tid + 256;
    int bc0 = tid, bc1 = tid + 256;

    float acc[4][4][4];
#pragma unroll
    for (int mt = 0; mt < 4; mt++)
#pragma unroll
        for (int nt = 0; nt < 4; nt++)
#pragma unroll
            for (int i = 0; i < 4; i++) acc[mt][nt][i] = 0.f;

    auto pf = [&](int t, int s) {
        int kt = t * BK;
#pragma unroll
        for (int p = 0; p < 2; p++) {
            int c = p ? ac1 : ac0;
            int row = c >> 2, kc = (c & 3) * 4;
            cp16(&As[s][row][kc], A + (size_t)(m0 + row) * K + kt + kc, 16);
        }
#pragma unroll
        for (int p = 0; p < 2; p++) {
            int c = p ? bc1 : bc0;
            int kr = c >> 5, nc = (c & 31) * 4;
            cp16(&Bs[s][kr][nc], B + (size_t)(kt + kr) * N + n0 + nc, 16);
        }
    };

    pf(0, 0);
    asm volatile("cp.async.commit_group;\n");

    const int ntiles = K / BK;  // 2
#pragma unroll
    for (int t = 0; t < ntiles; t++) {
        int s = t & 1;
        asm volatile("cp.async.wait_group 0;\n");
        __syncthreads();
        if (t + 1 < ntiles) pf(t + 1, s ^ 1);
        asm volatile("cp.async.commit_group;\n");

#pragma unroll
        for (int ks = 0; ks < 2; ks++) {
            int k0 = ks * 8;
            unsigned af[4][4], bf[4][2];
#pragma unroll
            for (int mt = 0; mt < 4; mt++) {
                int m = wm * 64 + mt * 16;
                af[mt][0] = f2tf(As[s][m + gid][k0 + tig]);
                af[mt][1] = f2tf(As[s][m + gid + 8][k0 + tig]);
                af[mt][2] = f2tf(As[s][m + gid][k0 + tig + 4]);
                af[mt][3] = f2tf(As[s][m + gid + 8][k0 + tig + 4]);
            }
#pragma unroll
            for (int nt = 0; nt < 4; nt++) {
                int n = wn * 32 + nt * 8;
                bf[nt][0] = f2tf(Bs[s][k0 + tig][n + gid]);
                bf[nt][1] = f2tf(Bs[s][k0 + tig + 4][n + gid]);
            }
#pragma unroll
            for (int mt = 0; mt < 4; mt++)
#pragma unroll
                for (int nt = 0; nt < 4; nt++) MMA_TF32(acc[mt][nt], af[mt], bf[nt]);
        }
        __syncthreads();
    }

    // --- fused logits epilogue: 2 passes of 64 edges, smem aliased over pool ---
    float (*Cs)[BN + 4] = (float(*)[BN + 4])pool;
#pragma unroll
    for (int pass = 0; pass < 2; pass++) {
        __syncthreads();
        if (wm == pass) {
#pragma unroll
            for (int mt = 0; mt < 4; mt++)
#pragma unroll
                for (int nt = 0; nt < 4; nt++) {
                    int cb = wn * 32 + nt * 8 + tig * 2;
#pragma unroll
                    for (int half = 0; half < 2; half++) {
                        int lr = mt * 16 + gid + half * 8;
                        Cs[lr][cb + 0] = acc[mt][nt][half * 2 + 0];
                        Cs[lr][cb + 1] = acc[mt][nt][half * 2 + 1];
                    }
                }
        }
        __syncthreads();

        float4 w = *(const float4*)&s_att[lane * 4];
        for (int eo = warp; eo < 64; eo += 8) {
            int ed = m0 + pass * 64 + eo;
            int src = ei[ed];
            int dst = ei[EE + ed];
            float4 ev = *(const float4*)&Cs[eo][lane * 4];
            float4 a = *(const float4*)(xl + (size_t)src * xls + n0 + lane * 4);
            float4 b = *(const float4*)(xr + (size_t)dst * xls + n0 + lane * 4);
            float u, p = 0.f;
            u = a.x + b.x + ev.x; u = u > 0.f ? u : 0.2f * u; p += u * w.x;
            u = a.y + b.y + ev.y; u = u > 0.f ? u : 0.2f * u; p += u * w.y;
            u = a.z + b.z + ev.z; u = u > 0.f ? u : 0.2f * u; p += u * w.z;
            u = a.w + b.w + ev.w; u = u > 0.f ? u : 0.2f * u; p += u * w.w;
#pragma unroll
            for (int o = 16; o; o >>= 1) p += __shfl_xor_sync(0xffffffffu, p, o);
            if (lane == 0) logit[(size_t)ed * H + head] = p;
        }
    }
}

// ---------------- self-loop logits: one warp per node -----------------------
template <int H>
__global__ void selflogits_kernel(const float* __restrict__ xl, const float* __restrict__ xr,
                                  int xls, const float* __restrict__ eself,
                                  const float* __restrict__ att, float* __restrict__ logit) {
    const int HC = H * 128;
    __shared__ float s_att[H * 128];
    for (int i = threadIdx.x; i < HC; i += blockDim.x) s_att[i] = att[i];
    __syncthreads();

    int n = (blockIdx.x * blockDim.x + threadIdx.x) >> 5;
    int lane = threadIdx.x & 31;
    if (n >= NN) return;
    const float4* pl = (const float4*)(xl + (size_t)n * xls);
    const float4* pr = (const float4*)(xr + (size_t)n * xls);
    const float4* pe = (const float4*)eself;
    const float4* pa = (const float4*)s_att;

#pragma unroll
    for (int h = 0; h < H; h++) {
        int j = h * 32 + lane;
        float4 a = pl[j], b = pr[j], c = pe[j], w = pa[j];
        float u, p = 0.f;
        u = a.x + b.x + c.x; u = u > 0.f ? u : 0.2f * u; p += u * w.x;
        u = a.y + b.y + c.y; u = u > 0.f ? u : 0.2f * u; p += u * w.y;
        u = a.z + b.z + c.z; u = u > 0.f ? u : 0.2f * u; p += u * w.z;
        u = a.w + b.w + c.w; u = u > 0.f ? u : 0.2f * u; p += u * w.w;
#pragma unroll
        for (int o = 16; o; o >>= 1) p += __shfl_xor_sync(0xffffffffu, p, o);
        if (lane == 0) logit[(size_t)(EE + n) * H + h] = p;
    }
}

// ---------------- node-parallel segment softmax + aggregation --------------
template <int H, int CONCAT, int ACT>
__global__ void agg_kernel(const float* __restrict__ xl, int xls,
                           const float* __restrict__ logit,
                           const int* __restrict__ ei, const float* __restrict__ bias,
                           const float* __restrict__ res, int rss,
                           float* __restrict__ out) {
    const int HC = H * 128;
    int n = blockIdx.x, t = threadIdx.x;
    int beg = g_off[n];
    int deg = g_off[n + 1] - beg;
    __shared__ float red[128];
    __shared__ float s_m[H], s_z[H];

    float lm[H];
#pragma unroll
    for (int h = 0; h < H; h++) lm[h] = -1e30f;
    for (int i = t; i < deg; i += 128) {
        int e = g_csr[beg + i];
#pragma unroll
        for (int h = 0; h < H; h++) lm[h] = fmaxf(lm[h], logit[(size_t)e * H + h]);
    }
#pragma unroll
    for (int h = 0; h < H; h++) {
        red[t] = lm[h];
        __syncthreads();
        for (int s = 64; s > 0; s >>= 1) {
            if (t < s) red[t] = fmaxf(red[t], red[t + s]);
            __syncthreads();
        }
        if (t == 0) s_m[h] = red[0];
        __syncthreads();
    }

    float lz[H];
#pragma unroll
    for (int h = 0; h < H; h++) lz[h] = 0.f;
    for (int i = t; i < deg; i += 128) {
        int e = g_csr[beg + i];
#pragma unroll
        for (int h = 0; h < H; h++) lz[h] += __expf(logit[(size_t)e * H + h] - s_m[h]);
    }
#pragma unroll
    for (int h = 0; h < H; h++) {
        red[t] = lz[h];
        __syncthreads();
        for (int s = 64; s > 0; s >>= 1) {
            if (t < s) red[t] += red[t + s];
            __syncthreads();
        }
        if (t == 0) s_z[h] = red[0];
        __syncthreads();
    }

    float acc[H];
#pragma unroll
    for (int h = 0; h < H; h++) acc[h] = 0.f;
    for (int i = 0; i < deg; i++) {
        int e = g_csr[beg + i];
        int src = (e < EE) ? ei[e] : (e - EE);
        const float* xp = xl + (size_t)src * xls;
#pragma unroll
        for (int h = 0; h < H; h++) {
            float w = __expf(logit[(size_t)e * H + h] - s_m[h]);
            acc[h] += w * xp[h * 128 + t];
        }
    }

    if (CONCAT) {
#pragma unroll
        for (int h = 0; h < H; h++) {
            float v = acc[h] / (s_z[h] + 1e-16f) + bias[h * 128 + t];
            if (res) v += res[(size_t)n * rss + h * 128 + t];
            if (ACT == 1) v = v > 0.f ? v : 0.2f * v;
            else if (ACT == 2) v = v > 0.f ? v : expm1f(v);
            out[(size_t)n * HC + h * 128 + t] = v;
        }
    } else {
        float v = 0.f;
#pragma unroll
        for (int h = 0; h < H; h++) v += acc[h] / (s_z[h] + 1e-16f);
        v = v * (1.f / H) + bias[t];
        if (ACT == 1) v = v > 0.f ? v : 0.2f * v;
        else if (ACT == 2) v = v > 0.f ? v : expm1f(v);
        out[(size_t)n * 128 + t] = v;
    }
}

// ---------------- final tiny GEMM [NN,64]x[64,3] ----------------------------
__global__ void head2_kernel(const float* __restrict__ t1, const float* __restrict__ W,
                             const float* __restrict__ b, float* __restrict__ out) {
    int gw = (blockIdx.x * blockDim.x + threadIdx.x) >> 5;
    int lane = threadIdx.x & 31;
    if (gw >= NN) return;
    float a0 = t1[(size_t)gw * 64 + lane];
    float a1 = t1[(size_t)gw * 64 + 32 + lane];
#pragma unroll
    for (int j = 0; j < 3; j++) {
        float p = a0 * W[lane * 3 + j] + a1 * W[(lane + 32) * 3 + j];
#pragma unroll
        for (int o = 16; o; o >>= 1) p += __shfl_xor_sync(0xffffffffu, p, o);
        if (lane == 0) out[(size_t)gw * 3 + j] = p + b[j];
    }
}

// ---------------- host orchestration ---------------------------------------
static inline void gemm(const float* A, const float* B, const float* bias, float* C,
                        int M, int N, int K, int act) {
    dim3 g((N + BN - 1) / BN, (M + BM - 1) / BM);
    gemm_tf32_kernel<<<g, 256, GSMEM>>>(A, B, bias, C, M, N, K, act);
}

extern "C" void kernel_launch(void* const* d_in, const int* in_sizes, int n_in,
                              void* d_out, int out_size) {
    const float* x    = (const float*)d_in[0];
    const int*   ei   = (const int*)d_in[1];
    const float* ea   = (const float*)d_in[2];
    const float* Wl1  = (const float*)d_in[3];
    const float* bl1  = (const float*)d_in[4];
    const float* Wr1  = (const float*)d_in[5];
    const float* br1  = (const float*)d_in[6];
    const float* We1  = (const float*)d_in[7];
    const float* att1 = (const float*)d_in[8];
    const float* bo1  = (const float*)d_in[9];
    const float* Wl2  = (const float*)d_in[10];
    const float* bl2  = (const float*)d_in[11];
    const float* Wr2  = (const float*)d_in[12];
    const float* br2  = (const float*)d_in[13];
    const float* We2  = (const float*)d_in[14];
    const float* att2 = (const float*)d_in[15];
    const float* bo2  = (const float*)d_in[16];
    const float* Wl3  = (const float*)d_in[17];
    const float* bl3  = (const float*)d_in[18];
    const float* Wr3  = (const float*)d_in[19];
    const float* br3  = (const float*)d_in[20];
    const float* We3  = (const float*)d_in[21];
    const float* att3 = (const float*)d_in[22];
    const float* bo3  = (const float*)d_in[23];
    const float* Wres = (const float*)d_in[24];
    const float* bres = (const float*)d_in[25];
    const float* Wc1  = (const float*)d_in[26];
    const float* bc1  = (const float*)d_in[27];
    const float* Wc2  = (const float*)d_in[28];
    const float* bc2  = (const float*)d_in[29];
    float* out = (float*)d_out;

    cudaFuncSetAttribute(gemm_tf32_kernel,
                         cudaFuncAttributeMaxDynamicSharedMemorySize, GSMEM);

    float *p_big, *p_h1, *p_h2, *p_h3, *p_t1, *p_w, *p_b, *p_eself, *p_lg;
    cudaGetSymbolAddress((void**)&p_big, g_big);
    cudaGetSymbolAddress((void**)&p_h1, g_h1);
    cudaGetSymbolAddress((void**)&p_h2, g_h2);
    cudaGetSymbolAddress((void**)&p_h3, g_h3);
    cudaGetSymbolAddress((void**)&p_t1, g_t1);
    cudaGetSymbolAddress((void**)&p_w, g_wcat);
    cudaGetSymbolAddress((void**)&p_b, g_bcat);
    cudaGetSymbolAddress((void**)&p_eself, g_eself);
    cudaGetSymbolAddress((void**)&p_lg, g_logit);

    // graph setup: mean edge attr + CSR by dst
    zero_kernel<<<(NN + 255) / 256, 256>>>();
    colsum_kernel<<<256, 256>>>(ea);
    hist_kernel<<<(ET + 255) / 256, 256>>>(ei);
    meanfin_kernel<<<1, 32>>>();
    scan_kernel<<<1, 1024>>>();
    scatter_kernel<<<(ET + 255) / 256, 256>>>(ei);

    const int SELF_GRID = (NN * 32 + 255) / 256;
    const cudaMemcpyKind DD = cudaMemcpyDeviceToDevice;

    // ---- layer 1: H=8, C=128, concat; then +res, leaky_relu ----
    // pack [Wl1 | Wr1 | Wres] -> [128, 3072]
    cudaMemcpy2DAsync(p_w,        3072 * 4, Wl1,  1024 * 4, 1024 * 4, 128, DD);
    cudaMemcpy2DAsync(p_w + 1024, 3072 * 4, Wr1,  1024 * 4, 1024 * 4, 128, DD);
    cudaMemcpy2DAsync(p_w + 2048, 3072 * 4, Wres, 1024 * 4, 1024 * 4, 128, DD);
    cudaMemcpyAsync(p_b,        bl1,  1024 * 4, DD);
    cudaMemcpyAsync(p_b + 1024, br1,  1024 * 4, DD);
    cudaMemcpyAsync(p_b + 2048, bres, 1024 * 4, DD);
    gemm(x, p_w, p_b, p_big, NN, 3072, 128, 0);
    eself_kernel<<<(1024 + 255) / 256, 256>>>(We1, 1024);
    {
        dim3 ge(1024 / BN, EE / BM);
        gemm_logits_kernel<<<ge, 256>>>(ea, We1, p_big, p_big + 1024, 3072,
                                        att1, ei, p_lg, 1024, 8);
    }
    selflogits_kernel<8><<<SELF_GRID, 256>>>(p_big, p_big + 1024, 3072, p_eself, att1, p_lg);
    agg_kernel<8, 1, 1><<<NN, 128>>>(p_big, 3072, p_lg, ei, bo1, p_big + 2048, 3072, p_h1);

    // ---- layer 2: H=4, C=128, mean; elu ----
    cudaMemcpy2DAsync(p_w,       1024 * 4, Wl2, 512 * 4, 512 * 4, 1024, DD);
    cudaMemcpy2DAsync(p_w + 512, 1024 * 4, Wr2, 512 * 4, 512 * 4, 1024, DD);
    cudaMemcpyAsync(p_b,       bl2, 512 * 4, DD);
    cudaMemcpyAsync(p_b + 512, br2, 512 * 4, DD);
    gemm(p_h1, p_w, p_b, p_big, NN, 1024, 1024, 0);
    eself_kernel<<<(512 + 255) / 256, 256>>>(We2, 512);
    {
        dim3 ge(512 / BN, EE / BM);
        gemm_logits_kernel<<<ge, 256>>>(ea, We2, p_big, p_big + 512, 1024,
                                        att2, ei, p_lg, 512, 4);
    }
    selflogits_kernel<4><<<SELF_GRID, 256>>>(p_big, p_big + 512, 1024, p_eself, att2, p_lg);
    agg_kernel<4, 0, 2><<<NN, 128>>>(p_big, 1024, p_lg, ei, bo2, nullptr, 0, p_h2);

    // ---- layer 3: H=1, C=128, concat; elu ----
    cudaMemcpy2DAsync(p_w,       256 * 4, Wl3, 128 * 4, 128 * 4, 128, DD);
    cudaMemcpy2DAsync(p_w + 128, 256 * 4, Wr3, 128 * 4, 128 * 4, 128, DD);
    cudaMemcpyAsync(p_b,       bl3, 128 * 4, DD);
    cudaMemcpyAsync(p_b + 128, br3, 128 * 4, DD);
    gemm(p_h2, p_w, p_b, p_big, NN, 256, 128, 0);
    eself_kernel<<<1, 128>>>(We3, 128);
    {
        dim3 ge(128 / BN, EE / BM);
        gemm_logits_kernel<<<ge, 256>>>(ea, We3, p_big, p_big + 128, 256,
                                        att3, ei, p_lg, 128, 1);
    }
    selflogits_kernel<1><<<SELF_GRID, 256>>>(p_big, p_big + 128, 256, p_eself, att3, p_lg);
    agg_kernel<1, 1, 2><<<NN, 128>>>(p_big, 256, p_lg, ei, bo3, nullptr, 0, p_h3);

    // ---- head MLP ----
    gemm(p_h3, Wc1, bc1, p_t1, NN, 64, 128, 1);  // + elu
    head2_kernel<<<(NN * 32 + 255) / 256, 256>>>(p_t1, Wc2, bc2, out);
}